// round 3
// baseline (speedup 1.0000x reference)
#include <cuda_runtime.h>

#define OBS_D 128
#define HID_D 256
#define ACT_D 32
#define NPOL 64
#define NBATCH 4096
#define BT 64           // batch-tile rows per CTA
#define KC 32           // K chunk for weight streaming
#define SSTR (HID_D + 4)  // 260, padded smem row stride (floats)
#define NTHREADS 512

typedef unsigned long long ull;

__device__ __forceinline__ ull pack2(float v) {
    ull r;
    asm("mov.b64 %0, {%1, %1};" : "=l"(r) : "f"(v));
    return r;
}
__device__ __forceinline__ void fma2(ull& d, ull a, ull b) {
    asm("fma.rn.f32x2 %0, %1, %2, %3;" : "=l"(d) : "l"(a), "l"(b), "l"(d));
}
__device__ __forceinline__ float2 unpack2(ull v) {
    float2 r;
    asm("mov.b64 {%0, %1}, %2;" : "=f"(r.x), "=f"(r.y) : "l"(v));
    return r;
}

// One hidden layer: sOut[64, 256] = GN(ELU?)(sIn[64, DIN] @ W[DIN,256] + b)
// 512 threads: tx = tid&31 (column pairs), ty = tid>>5 (row groups of 4).
template<int DIN, bool DOACT>
__device__ __forceinline__ void layer_hid(
    int tid,
    const float* __restrict__ Wp, const float* __restrict__ bp,
    const float* __restrict__ gp, const float* __restrict__ bep,
    const float* sIn, float* sOut, float* sW,
    float* sBias, float* sG, float* sBe)
{
    const int tx = tid & 31;
    const int ty = tid >> 5;   // 0..15 -> rows ty*4 .. ty*4+3

    if (tid < HID_D) {
        sBias[tid] = bp[tid];
        sG[tid]    = gp[tid];
        sBe[tid]   = bep[tid];
    }

    ull acc[4][4];
#pragma unroll
    for (int r = 0; r < 4; r++)
#pragma unroll
        for (int j = 0; j < 4; j++) acc[r][j] = 0ull;

    for (int kb = 0; kb < DIN; kb += KC) {
        __syncthreads();   // prior consumers of sW / producers of sIn done
        // cooperative load of W chunk [KC, 256] = 2048 float4
        {
            const float4* wsrc = (const float4*)(Wp + (size_t)kb * HID_D);
            float4* wdst = (float4*)sW;
#pragma unroll
            for (int i = 0; i < (KC * HID_D / 4) / NTHREADS; i++)
                wdst[tid + i * NTHREADS] = wsrc[tid + i * NTHREADS];
        }
        __syncthreads();
#pragma unroll
        for (int k = 0; k < KC; k++) {
            ull a[4];
#pragma unroll
            for (int r = 0; r < 4; r++)
                a[r] = pack2(sIn[(ty * 4 + r) * SSTR + kb + k]);
#pragma unroll
            for (int j = 0; j < 4; j++) {
                ull w = *(const ull*)(sW + k * HID_D + j * 64 + tx * 2);
#pragma unroll
                for (int r = 0; r < 4; r++) fma2(acc[r][j], a[r], w);
            }
        }
    }

    // bias add + store raw y to sOut
#pragma unroll
    for (int r = 0; r < 4; r++) {
#pragma unroll
        for (int j = 0; j < 4; j++) {
            int c = j * 64 + tx * 2;
            float2 v = unpack2(acc[r][j]);
            v.x += sBias[c];
            v.y += sBias[c + 1];
            *(float2*)(sOut + (ty * 4 + r) * SSTR + c) = v;
        }
    }
    __syncthreads();

    // GroupNorm over 256 per row + optional ELU, in place. 8 threads/row.
    {
        const int row = tid >> 3;
        const int sub = tid & 7;
        float* prow = sOut + row * SSTR;
        float s = 0.f, s2 = 0.f;
#pragma unroll
        for (int j = 0; j < HID_D / 8; j++) {
            float v = prow[j * 8 + sub];
            s += v; s2 += v * v;
        }
        s  += __shfl_xor_sync(0xffffffffu, s, 1);
        s2 += __shfl_xor_sync(0xffffffffu, s2, 1);
        s  += __shfl_xor_sync(0xffffffffu, s, 2);
        s2 += __shfl_xor_sync(0xffffffffu, s2, 2);
        s  += __shfl_xor_sync(0xffffffffu, s, 4);
        s2 += __shfl_xor_sync(0xffffffffu, s2, 4);
        float mu   = s * (1.f / HID_D);
        float var  = fmaxf(s2 * (1.f / HID_D) - mu * mu, 0.f);
        float rstd = rsqrtf(var + 1e-5f);
#pragma unroll
        for (int j = 0; j < HID_D / 8; j++) {
            int c = j * 8 + sub;
            float v = (prow[c] - mu) * rstd * sG[c] + sBe[c];
            if (DOACT) v = (v > 0.f) ? v : expm1f(v);
            prow[c] = v;
        }
    }
    __syncthreads();
}

// Final layer: out[64, 32] = GN(sIn[64,256] @ W4[256,32] + b4), no activation.
// 512 threads: row = tid>>3 (64 rows), sub = tid&7 (4 cols each as 2 pairs).
__device__ __forceinline__ void layer_out(
    int tid, int p, int b0,
    const float* __restrict__ Wp, const float* __restrict__ bp,
    const float* __restrict__ gp, const float* __restrict__ bep,
    const float* sIn, float* sW,
    float* sBias, float* sG, float* sBe,
    float* __restrict__ out)
{
    if (tid < ACT_D) {
        sBias[tid] = bp[tid];
        sG[tid]    = gp[tid];
        sBe[tid]   = bep[tid];
    }
    const int row = tid >> 3;
    const int sub = tid & 7;

    ull acc0 = 0ull, acc1 = 0ull;
    for (int kb = 0; kb < HID_D; kb += KC) {
        __syncthreads();
        if (tid < (KC * ACT_D / 4))   // 256 float4
            ((float4*)sW)[tid] = ((const float4*)(Wp + (size_t)kb * ACT_D))[tid];
        __syncthreads();
#pragma unroll
        for (int k = 0; k < KC; k++) {
            ull a = pack2(sIn[row * SSTR + kb + k]);
            fma2(acc0, a, *(const ull*)(sW + k * ACT_D + sub * 4));
            fma2(acc1, a, *(const ull*)(sW + k * ACT_D + sub * 4 + 2));
        }
    }

    float2 v0 = unpack2(acc0), v1 = unpack2(acc1);
    const int c0 = sub * 4;
    v0.x += sBias[c0];     v0.y += sBias[c0 + 1];
    v1.x += sBias[c0 + 2]; v1.y += sBias[c0 + 3];

    float s  = v0.x + v0.y + v1.x + v1.y;
    float s2 = v0.x * v0.x + v0.y * v0.y + v1.x * v1.x + v1.y * v1.y;
    s  += __shfl_xor_sync(0xffffffffu, s, 1);
    s2 += __shfl_xor_sync(0xffffffffu, s2, 1);
    s  += __shfl_xor_sync(0xffffffffu, s, 2);
    s2 += __shfl_xor_sync(0xffffffffu, s2, 2);
    s  += __shfl_xor_sync(0xffffffffu, s, 4);
    s2 += __shfl_xor_sync(0xffffffffu, s2, 4);
    float mu   = s * (1.f / ACT_D);
    float var  = fmaxf(s2 * (1.f / ACT_D) - mu * mu, 0.f);
    float rstd = rsqrtf(var + 1e-5f);

    float2 o0, o1;
    o0.x = (v0.x - mu) * rstd * sG[c0]     + sBe[c0];
    o0.y = (v0.y - mu) * rstd * sG[c0 + 1] + sBe[c0 + 1];
    o1.x = (v1.x - mu) * rstd * sG[c0 + 2] + sBe[c0 + 2];
    o1.y = (v1.y - mu) * rstd * sG[c0 + 3] + sBe[c0 + 3];

    float* orow = out + (size_t)(b0 + row) * (NPOL * ACT_D) + (size_t)p * ACT_D;
    *(float2*)(orow + c0)     = o0;
    *(float2*)(orow + c0 + 2) = o1;
}

__global__ void __launch_bounds__(NTHREADS, 1)
mlp_fused_kernel(
    const float* __restrict__ obs,
    const float* __restrict__ W1, const float* __restrict__ b1,
    const float* __restrict__ g1, const float* __restrict__ be1,
    const float* __restrict__ W2, const float* __restrict__ b2,
    const float* __restrict__ g2, const float* __restrict__ be2,
    const float* __restrict__ W3, const float* __restrict__ b3,
    const float* __restrict__ g3, const float* __restrict__ be3,
    const float* __restrict__ W4, const float* __restrict__ b4,
    const float* __restrict__ g4, const float* __restrict__ be4,
    float* __restrict__ out)
{
    extern __shared__ float smem[];
    float* sA    = smem;                    // BT * SSTR
    float* sB    = sA + BT * SSTR;          // BT * SSTR
    float* sW    = sB + BT * SSTR;          // KC * HID_D
    float* sBias = sW + KC * HID_D;         // HID_D
    float* sG    = sBias + HID_D;           // HID_D
    float* sBe   = sG + HID_D;              // HID_D

    const int tid = threadIdx.x;
    const int p   = blockIdx.y;
    const int b0  = blockIdx.x * BT;

    // Load observation tile [BT, 128] into sA (broadcast across policies).
    {
        const float4* src = (const float4*)(obs + (size_t)b0 * OBS_D);
#pragma unroll
        for (int i = 0; i < (BT * OBS_D / 4) / NTHREADS; i++) {  // 4 iters
            int idx = tid + i * NTHREADS;
            int row = idx >> 5;        // OBS_D/4 = 32 float4 per row
            int c4  = idx & 31;
            // row*SSTR floats = row*1040 bytes, 16B aligned (1040 = 65*16)
            ((float4*)(sA + row * SSTR))[c4] = src[idx];
        }
    }
    // (visibility guaranteed by the __syncthreads at top of first K-chunk)

    const size_t pO = (size_t)p;
    layer_hid<OBS_D, true >(tid, W1 + pO * OBS_D * HID_D, b1 + pO * HID_D,
                            g1 + pO * HID_D, be1 + pO * HID_D,
                            sA, sB, sW, sBias, sG, sBe);
    layer_hid<HID_D, true >(tid, W2 + pO * HID_D * HID_D, b2 + pO * HID_D,
                            g2 + pO * HID_D, be2 + pO * HID_D,
                            sB, sA, sW, sBias, sG, sBe);
    layer_hid<HID_D, true >(tid, W3 + pO * HID_D * HID_D, b3 + pO * HID_D,
                            g3 + pO * HID_D, be3 + pO * HID_D,
                            sA, sB, sW, sBias, sG, sBe);
    layer_out(tid, p, b0, W4 + pO * HID_D * ACT_D, b4 + pO * ACT_D,
              g4 + pO * ACT_D, be4 + pO * ACT_D,
              sB, sW, sBias, sG, sBe, out);
}

extern "C" void kernel_launch(void* const* d_in, const int* in_sizes, int n_in,
                              void* d_out, int out_size)
{
    const float* obs = (const float*)d_in[0];
    const float* W1  = (const float*)d_in[1];
    const float* b1  = (const float*)d_in[2];
    const float* g1  = (const float*)d_in[3];
    const float* be1 = (const float*)d_in[4];
    const float* W2  = (const float*)d_in[5];
    const float* b2  = (const float*)d_in[6];
    const float* g2  = (const float*)d_in[7];
    const float* be2 = (const float*)d_in[8];
    const float* W3  = (const float*)d_in[9];
    const float* b3  = (const float*)d_in[10];
    const float* g3  = (const float*)d_in[11];
    const float* be3 = (const float*)d_in[12];
    const float* W4  = (const float*)d_in[13];
    const float* b4  = (const float*)d_in[14];
    const float* g4  = (const float*)d_in[15];
    const float* be4 = (const float*)d_in[16];
    float* out = (float*)d_out;

    const int smem_bytes = (2 * BT * SSTR + KC * HID_D + 3 * HID_D) * (int)sizeof(float);
    cudaFuncSetAttribute(mlp_fused_kernel,
                         cudaFuncAttributeMaxDynamicSharedMemorySize, smem_bytes);

    dim3 grid(NBATCH / BT, NPOL);   // 64 x 64 = 4096 CTAs
    mlp_fused_kernel<<<grid, NTHREADS, smem_bytes>>>(
        obs,
        W1, b1, g1, be1,
        W2, b2, g2, be2,
        W3, b3, g3, be3,
        W4, b4, g4, be4,
        out);
}

// round 4
// speedup vs baseline: 1.0006x; 1.0006x over previous
#include <cuda_runtime.h>

#define OBS_D 128
#define HID_D 256
#define ACT_D 32
#define NPOL 64
#define NBATCH 4096
#define BT 64           // batch-tile rows per CTA
#define KC 32           // K chunk for weight streaming
#define SSTR (HID_D + 4)  // 260, padded smem row stride (floats)
#define NTHREADS 512

typedef unsigned long long ull;

__device__ __forceinline__ ull pack2(float v) {
    ull r;
    asm("mov.b64 %0, {%1, %1};" : "=l"(r) : "f"(v));
    return r;
}
__device__ __forceinline__ void fma2(ull& d, ull a, ull b) {
    asm("fma.rn.f32x2 %0, %1, %2, %3;" : "=l"(d) : "l"(a), "l"(b), "l"(d));
}
__device__ __forceinline__ float2 unpack2(ull v) {
    float2 r;
    asm("mov.b64 {%0, %1}, %2;" : "=f"(r.x), "=f"(r.y) : "l"(v));
    return r;
}

// One hidden layer: sOut[64, 256] = GN(ELU?)(sIn[64, DIN] @ W[DIN,256] + b)
// 512 threads: tx = tid&31 (column pairs), ty = tid>>5 (row groups of 4).
template<int DIN, bool DOACT>
__device__ __forceinline__ void layer_hid(
    int tid,
    const float* __restrict__ Wp, const float* __restrict__ bp,
    const float* __restrict__ gp, const float* __restrict__ bep,
    const float* sIn, float* sOut, float* sW,
    float* sBias, float* sG, float* sBe)
{
    const int tx = tid & 31;
    const int ty = tid >> 5;   // 0..15 -> rows ty*4 .. ty*4+3

    if (tid < HID_D) {
        sBias[tid] = bp[tid];
        sG[tid]    = gp[tid];
        sBe[tid]   = bep[tid];
    }

    ull acc[4][4];
#pragma unroll
    for (int r = 0; r < 4; r++)
#pragma unroll
        for (int j = 0; j < 4; j++) acc[r][j] = 0ull;

    for (int kb = 0; kb < DIN; kb += KC) {
        __syncthreads();   // prior consumers of sW / producers of sIn done
        // cooperative load of W chunk [KC, 256] = 2048 float4
        {
            const float4* wsrc = (const float4*)(Wp + (size_t)kb * HID_D);
            float4* wdst = (float4*)sW;
#pragma unroll
            for (int i = 0; i < (KC * HID_D / 4) / NTHREADS; i++)
                wdst[tid + i * NTHREADS] = wsrc[tid + i * NTHREADS];
        }
        __syncthreads();
#pragma unroll
        for (int k = 0; k < KC; k++) {
            ull a[4];
#pragma unroll
            for (int r = 0; r < 4; r++)
                a[r] = pack2(sIn[(ty * 4 + r) * SSTR + kb + k]);
#pragma unroll
            for (int j = 0; j < 4; j++) {
                ull w = *(const ull*)(sW + k * HID_D + j * 64 + tx * 2);
#pragma unroll
                for (int r = 0; r < 4; r++) fma2(acc[r][j], a[r], w);
            }
        }
    }

    // bias add + store raw y to sOut
#pragma unroll
    for (int r = 0; r < 4; r++) {
#pragma unroll
        for (int j = 0; j < 4; j++) {
            int c = j * 64 + tx * 2;
            float2 v = unpack2(acc[r][j]);
            v.x += sBias[c];
            v.y += sBias[c + 1];
            *(float2*)(sOut + (ty * 4 + r) * SSTR + c) = v;
        }
    }
    __syncthreads();

    // GroupNorm over 256 per row + optional ELU, in place. 8 threads/row.
    {
        const int row = tid >> 3;
        const int sub = tid & 7;
        float* prow = sOut + row * SSTR;
        float s = 0.f, s2 = 0.f;
#pragma unroll
        for (int j = 0; j < HID_D / 8; j++) {
            float v = prow[j * 8 + sub];
            s += v; s2 += v * v;
        }
        s  += __shfl_xor_sync(0xffffffffu, s, 1);
        s2 += __shfl_xor_sync(0xffffffffu, s2, 1);
        s  += __shfl_xor_sync(0xffffffffu, s, 2);
        s2 += __shfl_xor_sync(0xffffffffu, s2, 2);
        s  += __shfl_xor_sync(0xffffffffu, s, 4);
        s2 += __shfl_xor_sync(0xffffffffu, s2, 4);
        float mu   = s * (1.f / HID_D);
        float var  = fmaxf(s2 * (1.f / HID_D) - mu * mu, 0.f);
        float rstd = rsqrtf(var + 1e-5f);
#pragma unroll
        for (int j = 0; j < HID_D / 8; j++) {
            int c = j * 8 + sub;
            float v = (prow[c] - mu) * rstd * sG[c] + sBe[c];
            if (DOACT) v = (v > 0.f) ? v : expm1f(v);
            prow[c] = v;
        }
    }
    __syncthreads();
}

// Final layer: out[64, 32] = GN(sIn[64,256] @ W4[256,32] + b4), no activation.
// 512 threads: row = tid>>3 (64 rows), sub = tid&7 (4 cols each as 2 pairs).
__device__ __forceinline__ void layer_out(
    int tid, int p, int b0,
    const float* __restrict__ Wp, const float* __restrict__ bp,
    const float* __restrict__ gp, const float* __restrict__ bep,
    const float* sIn, float* sW,
    float* sBias, float* sG, float* sBe,
    float* __restrict__ out)
{
    if (tid < ACT_D) {
        sBias[tid] = bp[tid];
        sG[tid]    = gp[tid];
        sBe[tid]   = bep[tid];
    }
    const int row = tid >> 3;
    const int sub = tid & 7;

    ull acc0 = 0ull, acc1 = 0ull;
    for (int kb = 0; kb < HID_D; kb += KC) {
        __syncthreads();
        if (tid < (KC * ACT_D / 4))   // 256 float4
            ((float4*)sW)[tid] = ((const float4*)(Wp + (size_t)kb * ACT_D))[tid];
        __syncthreads();
#pragma unroll
        for (int k = 0; k < KC; k++) {
            ull a = pack2(sIn[row * SSTR + kb + k]);
            fma2(acc0, a, *(const ull*)(sW + k * ACT_D + sub * 4));
            fma2(acc1, a, *(const ull*)(sW + k * ACT_D + sub * 4 + 2));
        }
    }

    float2 v0 = unpack2(acc0), v1 = unpack2(acc1);
    const int c0 = sub * 4;
    v0.x += sBias[c0];     v0.y += sBias[c0 + 1];
    v1.x += sBias[c0 + 2]; v1.y += sBias[c0 + 3];

    float s  = v0.x + v0.y + v1.x + v1.y;
    float s2 = v0.x * v0.x + v0.y * v0.y + v1.x * v1.x + v1.y * v1.y;
    s  += __shfl_xor_sync(0xffffffffu, s, 1);
    s2 += __shfl_xor_sync(0xffffffffu, s2, 1);
    s  += __shfl_xor_sync(0xffffffffu, s, 2);
    s2 += __shfl_xor_sync(0xffffffffu, s2, 2);
    s  += __shfl_xor_sync(0xffffffffu, s, 4);
    s2 += __shfl_xor_sync(0xffffffffu, s2, 4);
    float mu   = s * (1.f / ACT_D);
    float var  = fmaxf(s2 * (1.f / ACT_D) - mu * mu, 0.f);
    float rstd = rsqrtf(var + 1e-5f);

    float2 o0, o1;
    o0.x = (v0.x - mu) * rstd * sG[c0]     + sBe[c0];
    o0.y = (v0.y - mu) * rstd * sG[c0 + 1] + sBe[c0 + 1];
    o1.x = (v1.x - mu) * rstd * sG[c0 + 2] + sBe[c0 + 2];
    o1.y = (v1.y - mu) * rstd * sG[c0 + 3] + sBe[c0 + 3];

    float* orow = out + (size_t)(b0 + row) * (NPOL * ACT_D) + (size_t)p * ACT_D;
    *(float2*)(orow + c0)     = o0;
    *(float2*)(orow + c0 + 2) = o1;
}

__global__ void __launch_bounds__(NTHREADS, 1)
mlp_fused_kernel(
    const float* __restrict__ obs,
    const float* __restrict__ W1, const float* __restrict__ b1,
    const float* __restrict__ g1, const float* __restrict__ be1,
    const float* __restrict__ W2, const float* __restrict__ b2,
    const float* __restrict__ g2, const float* __restrict__ be2,
    const float* __restrict__ W3, const float* __restrict__ b3,
    const float* __restrict__ g3, const float* __restrict__ be3,
    const float* __restrict__ W4, const float* __restrict__ b4,
    const float* __restrict__ g4, const float* __restrict__ be4,
    float* __restrict__ out)
{
    extern __shared__ float smem[];
    float* sA    = smem;                    // BT * SSTR
    float* sB    = sA + BT * SSTR;          // BT * SSTR
    float* sW    = sB + BT * SSTR;          // KC * HID_D
    float* sBias = sW + KC * HID_D;         // HID_D
    float* sG    = sBias + HID_D;           // HID_D
    float* sBe   = sG + HID_D;              // HID_D

    const int tid = threadIdx.x;
    const int p   = blockIdx.y;
    const int b0  = blockIdx.x * BT;

    // Load observation tile [BT, 128] into sA (broadcast across policies).
    {
        const float4* src = (const float4*)(obs + (size_t)b0 * OBS_D);
#pragma unroll
        for (int i = 0; i < (BT * OBS_D / 4) / NTHREADS; i++) {  // 4 iters
            int idx = tid + i * NTHREADS;
            int row = idx >> 5;        // OBS_D/4 = 32 float4 per row
            int c4  = idx & 31;
            // row*SSTR floats = row*1040 bytes, 16B aligned (1040 = 65*16)
            ((float4*)(sA + row * SSTR))[c4] = src[idx];
        }
    }
    // (visibility guaranteed by the __syncthreads at top of first K-chunk)

    const size_t pO = (size_t)p;
    layer_hid<OBS_D, true >(tid, W1 + pO * OBS_D * HID_D, b1 + pO * HID_D,
                            g1 + pO * HID_D, be1 + pO * HID_D,
                            sA, sB, sW, sBias, sG, sBe);
    layer_hid<HID_D, true >(tid, W2 + pO * HID_D * HID_D, b2 + pO * HID_D,
                            g2 + pO * HID_D, be2 + pO * HID_D,
                            sB, sA, sW, sBias, sG, sBe);
    layer_hid<HID_D, true >(tid, W3 + pO * HID_D * HID_D, b3 + pO * HID_D,
                            g3 + pO * HID_D, be3 + pO * HID_D,
                            sA, sB, sW, sBias, sG, sBe);
    layer_out(tid, p, b0, W4 + pO * HID_D * ACT_D, b4 + pO * ACT_D,
              g4 + pO * ACT_D, be4 + pO * ACT_D,
              sB, sW, sBias, sG, sBe, out);
}

extern "C" void kernel_launch(void* const* d_in, const int* in_sizes, int n_in,
                              void* d_out, int out_size)
{
    const float* obs = (const float*)d_in[0];
    const float* W1  = (const float*)d_in[1];
    const float* b1  = (const float*)d_in[2];
    const float* g1  = (const float*)d_in[3];
    const float* be1 = (const float*)d_in[4];
    const float* W2  = (const float*)d_in[5];
    const float* b2  = (const float*)d_in[6];
    const float* g2  = (const float*)d_in[7];
    const float* be2 = (const float*)d_in[8];
    const float* W3  = (const float*)d_in[9];
    const float* b3  = (const float*)d_in[10];
    const float* g3  = (const float*)d_in[11];
    const float* be3 = (const float*)d_in[12];
    const float* W4  = (const float*)d_in[13];
    const float* b4  = (const float*)d_in[14];
    const float* g4  = (const float*)d_in[15];
    const float* be4 = (const float*)d_in[16];
    float* out = (float*)d_out;

    const int smem_bytes = (2 * BT * SSTR + KC * HID_D + 3 * HID_D) * (int)sizeof(float);
    cudaFuncSetAttribute(mlp_fused_kernel,
                         cudaFuncAttributeMaxDynamicSharedMemorySize, smem_bytes);

    dim3 grid(NBATCH / BT, NPOL);   // 64 x 64 = 4096 CTAs
    mlp_fused_kernel<<<grid, NTHREADS, smem_bytes>>>(
        obs,
        W1, b1, g1, be1,
        W2, b2, g2, be2,
        W3, b3, g3, be3,
        W4, b4, g4, be4,
        out);
}

// round 6
// speedup vs baseline: 1.1281x; 1.1275x over previous
#include <cuda_runtime.h>
#include <cstdint>

#define OBS_D 128
#define HID_D 256
#define ACT_D 32
#define NPOL 64
#define NBATCH 4096
#define BT 64             // batch-tile rows per CTA
#define KC 32             // K chunk for weight streaming
#define SSTR (HID_D + 4)  // 260, padded smem row stride (floats)
#define NTHREADS 512

typedef unsigned long long ull;

__device__ __forceinline__ ull pack2(float v) {
    ull r;
    asm("mov.b64 %0, {%1, %1};" : "=l"(r) : "f"(v));
    return r;
}
__device__ __forceinline__ ull packf2(float x, float y) {
    ull r;
    asm("mov.b64 %0, {%1, %2};" : "=l"(r) : "f"(x), "f"(y));
    return r;
}
__device__ __forceinline__ void fma2(ull& d, ull a, ull b) {
    asm("fma.rn.f32x2 %0, %1, %2, %3;" : "=l"(d) : "l"(a), "l"(b), "l"(d));
}
__device__ __forceinline__ float2 unpack2(ull v) {
    float2 r;
    asm("mov.b64 {%0, %1}, %2;" : "=f"(r.x), "=f"(r.y) : "l"(v));
    return r;
}
__device__ __forceinline__ void cp_async16(uint32_t saddr, const void* gptr) {
    asm volatile("cp.async.cg.shared.global [%0], [%1], 16;" :: "r"(saddr), "l"(gptr));
}
__device__ __forceinline__ void cp_commit() {
    asm volatile("cp.async.commit_group;");
}
template<int N>
__device__ __forceinline__ void cp_wait() {
    asm volatile("cp.async.wait_group %0;" :: "n"(N));
}

// One hidden layer: sOut[64,256] = GN(+ELU?)(sIn[64,DIN] @ W[DIN,256] + b)
// 16 warps: rg = warp&7 -> 8 rows each; ch = warp>>3 -> 128-col half.
// Per thread: 8 rows x 2 column-pairs (acc[8][2] f32x2).
template<int DIN, bool DOACT>
__device__ __forceinline__ void layer_hid(
    int tid,
    const float* __restrict__ Wp, const float* __restrict__ bp,
    const float* __restrict__ gp, const float* __restrict__ bep,
    const float* sIn, float* sOut, float* sW0, float* sW1,
    float* sBias, float* sG, float* sBe)
{
    const int lane = tid & 31;
    const int w    = tid >> 5;
    const int row0 = (w & 7) * 8;           // 8 rows per row-group
    const int cb   = (w >> 3) * 128 + lane * 2;  // column base (pair)

    if (tid < HID_D) {
        sBias[tid] = bp[tid];
        sG[tid]    = gp[tid];
        sBe[tid]   = bep[tid];
    }

    // Prologue: async-copy weight chunk 0 into sW0.
    {
        uint32_t s = (uint32_t)__cvta_generic_to_shared(sW0) + (uint32_t)tid * 16u;
        const float4* g = (const float4*)Wp + tid;
#pragma unroll
        for (int i = 0; i < (KC * HID_D / 4) / NTHREADS; i++)
            cp_async16(s + i * NTHREADS * 16, g + i * NTHREADS);
        cp_commit();
    }

    ull acc[8][2];
#pragma unroll
    for (int r = 0; r < 8; r++) { acc[r][0] = 0ull; acc[r][1] = 0ull; }

    const int NCH = DIN / KC;
    for (int c = 0; c < NCH; c++) {
        const float* sWc = (c & 1) ? sW1 : sW0;
        float*       sWn = (c & 1) ? sW0 : sW1;

        if (c + 1 < NCH) {
            // prefetch next chunk into the other buffer (its old readers
            // finished at the end-of-iteration barrier of iter c-1)
            uint32_t s = (uint32_t)__cvta_generic_to_shared(sWn) + (uint32_t)tid * 16u;
            const float4* g = (const float4*)(Wp + (size_t)(c + 1) * KC * HID_D) + tid;
#pragma unroll
            for (int i = 0; i < (KC * HID_D / 4) / NTHREADS; i++)
                cp_async16(s + i * NTHREADS * 16, g + i * NTHREADS);
            cp_commit();
            cp_wait<1>();   // chunk c complete (chunk c+1 may be in flight)
        } else {
            cp_wait<0>();
        }
        __syncthreads();

        const int kb = c * KC;
#pragma unroll
        for (int k4 = 0; k4 < KC; k4 += 4) {
            float4 a4[8];
#pragma unroll
            for (int r = 0; r < 8; r++)
                a4[r] = *(const float4*)(sIn + (row0 + r) * SSTR + kb + k4);
#pragma unroll
            for (int kk = 0; kk < 4; kk++) {
                ull w0 = *(const ull*)(sWc + (k4 + kk) * HID_D + cb);
                ull w1 = *(const ull*)(sWc + (k4 + kk) * HID_D + cb + 64);
#pragma unroll
                for (int r = 0; r < 8; r++) {
                    float av = (kk == 0) ? a4[r].x : (kk == 1) ? a4[r].y
                             : (kk == 2) ? a4[r].z : a4[r].w;
                    ull a = pack2(av);
                    fma2(acc[r][0], a, w0);
                    fma2(acc[r][1], a, w1);
                }
            }
        }
        __syncthreads();   // protect sWc from next iteration's cp.async
    }

    // bias add + store raw y to sOut
#pragma unroll
    for (int r = 0; r < 8; r++) {
#pragma unroll
        for (int j = 0; j < 2; j++) {
            int cc = cb + j * 64;
            float2 v = unpack2(acc[r][j]);
            v.x += sBias[cc];
            v.y += sBias[cc + 1];
            *(float2*)(sOut + (row0 + r) * SSTR + cc) = v;
        }
    }
    __syncthreads();

    // GroupNorm over 256 per row (+ ELU), single read pass held in regs.
    // 8 threads per row, float4 vectorized.
    {
        const int row = tid >> 3;
        const int sub = tid & 7;
        float* prow = sOut + row * SSTR;
        float4 vv[8];
        float s = 0.f, s2 = 0.f;
#pragma unroll
        for (int j = 0; j < 8; j++) {
            vv[j] = *(const float4*)(prow + j * 32 + sub * 4);
            s  += vv[j].x + vv[j].y + vv[j].z + vv[j].w;
            s2 += vv[j].x * vv[j].x + vv[j].y * vv[j].y
                + vv[j].z * vv[j].z + vv[j].w * vv[j].w;
        }
        s  += __shfl_xor_sync(0xffffffffu, s, 1);
        s2 += __shfl_xor_sync(0xffffffffu, s2, 1);
        s  += __shfl_xor_sync(0xffffffffu, s, 2);
        s2 += __shfl_xor_sync(0xffffffffu, s2, 2);
        s  += __shfl_xor_sync(0xffffffffu, s, 4);
        s2 += __shfl_xor_sync(0xffffffffu, s2, 4);
        float mu   = s * (1.f / HID_D);
        float var  = fmaxf(s2 * (1.f / HID_D) - mu * mu, 0.f);
        float rstd = rsqrtf(var + 1e-5f);
#pragma unroll
        for (int j = 0; j < 8; j++) {
            int cc = j * 32 + sub * 4;
            float4 gg = *(const float4*)(sG + cc);
            float4 bb = *(const float4*)(sBe + cc);
            float4 o;
            o.x = (vv[j].x - mu) * rstd * gg.x + bb.x;
            o.y = (vv[j].y - mu) * rstd * gg.y + bb.y;
            o.z = (vv[j].z - mu) * rstd * gg.z + bb.z;
            o.w = (vv[j].w - mu) * rstd * gg.w + bb.w;
            if (DOACT) {
                o.x = (o.x > 0.f) ? o.x : expm1f(o.x);
                o.y = (o.y > 0.f) ? o.y : expm1f(o.y);
                o.z = (o.z > 0.f) ? o.z : expm1f(o.z);
                o.w = (o.w > 0.f) ? o.w : expm1f(o.w);
            }
            *(float4*)(prow + cc) = o;
        }
    }
    __syncthreads();
}

// Final layer: out[64,32] = GN(sIn[64,256] @ W4[256,32] + b4), no activation.
// All of W4 (32KB) loaded into smem once. row = tid>>3, sub = tid&7 (4 cols).
__device__ __forceinline__ void layer_out(
    int tid, int p, int b0,
    const float* __restrict__ Wp, const float* __restrict__ bp,
    const float* __restrict__ gp, const float* __restrict__ bep,
    const float* sIn, float* sW,
    float* sBias, float* sG, float* sBe,
    float* __restrict__ out)
{
    if (tid < ACT_D) {
        sBias[tid] = bp[tid];
        sG[tid]    = gp[tid];
        sBe[tid]   = bep[tid];
    }
    // Load entire W4 [256,32] = 2048 float4
#pragma unroll
    for (int i = 0; i < (HID_D * ACT_D / 4) / NTHREADS; i++)
        ((float4*)sW)[tid + i * NTHREADS] = ((const float4*)Wp)[tid + i * NTHREADS];
    __syncthreads();

    const int row = tid >> 3;
    const int sub = tid & 7;
    const int c0  = sub * 4;

    ull acc0 = 0ull, acc1 = 0ull;
#pragma unroll 4
    for (int k4 = 0; k4 < HID_D; k4 += 4) {
        float4 a4 = *(const float4*)(sIn + row * SSTR + k4);
#pragma unroll
        for (int kk = 0; kk < 4; kk++) {
            float4 wv = *(const float4*)(sW + (k4 + kk) * ACT_D + c0);
            ull w01 = packf2(wv.x, wv.y);
            ull w23 = packf2(wv.z, wv.w);
            float av = (kk == 0) ? a4.x : (kk == 1) ? a4.y
                     : (kk == 2) ? a4.z : a4.w;
            ull a = pack2(av);
            fma2(acc0, a, w01);
            fma2(acc1, a, w23);
        }
    }

    float2 v0 = unpack2(acc0), v1 = unpack2(acc1);
    v0.x += sBias[c0];     v0.y += sBias[c0 + 1];
    v1.x += sBias[c0 + 2]; v1.y += sBias[c0 + 3];

    float s  = v0.x + v0.y + v1.x + v1.y;
    float s2 = v0.x * v0.x + v0.y * v0.y + v1.x * v1.x + v1.y * v1.y;
    s  += __shfl_xor_sync(0xffffffffu, s, 1);
    s2 += __shfl_xor_sync(0xffffffffu, s2, 1);
    s  += __shfl_xor_sync(0xffffffffu, s, 2);
    s2 += __shfl_xor_sync(0xffffffffu, s2, 2);
    s  += __shfl_xor_sync(0xffffffffu, s, 4);
    s2 += __shfl_xor_sync(0xffffffffu, s2, 4);
    float mu   = s * (1.f / ACT_D);
    float var  = fmaxf(s2 * (1.f / ACT_D) - mu * mu, 0.f);
    float rstd = rsqrtf(var + 1e-5f);

    float2 o0, o1;
    o0.x = (v0.x - mu) * rstd * sG[c0]     + sBe[c0];
    o0.y = (v0.y - mu) * rstd * sG[c0 + 1] + sBe[c0 + 1];
    o1.x = (v1.x - mu) * rstd * sG[c0 + 2] + sBe[c0 + 2];
    o1.y = (v1.y - mu) * rstd * sG[c0 + 3] + sBe[c0 + 3];

    float* orow = out + (size_t)(b0 + row) * (NPOL * ACT_D) + (size_t)p * ACT_D;
    *(float2*)(orow + c0)     = o0;
    *(float2*)(orow + c0 + 2) = o1;
}

__global__ void __launch_bounds__(NTHREADS, 1)
mlp_fused_kernel(
    const float* __restrict__ obs,
    const float* __restrict__ W1, const float* __restrict__ b1,
    const float* __restrict__ g1, const float* __restrict__ be1,
    const float* __restrict__ W2, const float* __restrict__ b2,
    const float* __restrict__ g2, const float* __restrict__ be2,
    const float* __restrict__ W3, const float* __restrict__ b3,
    const float* __restrict__ g3, const float* __restrict__ be3,
    const float* __restrict__ W4, const float* __restrict__ b4,
    const float* __restrict__ g4, const float* __restrict__ be4,
    float* __restrict__ out)
{
    extern __shared__ float smem[];
    float* sA    = smem;                    // BT * SSTR
    float* sB    = sA + BT * SSTR;          // BT * SSTR
    float* sW0   = sB + BT * SSTR;          // KC * HID_D
    float* sW1   = sW0 + KC * HID_D;        // KC * HID_D
    float* sBias = sW1 + KC * HID_D;        // HID_D
    float* sG    = sBias + HID_D;           // HID_D
    float* sBe   = sG + HID_D;              // HID_D

    const int tid = threadIdx.x;
    const int p   = blockIdx.y;
    const int b0  = blockIdx.x * BT;

    // Load observation tile [BT, 128] into sA.
    {
        const float4* src = (const float4*)(obs + (size_t)b0 * OBS_D);
#pragma unroll
        for (int i = 0; i < (BT * OBS_D / 4) / NTHREADS; i++) {  // 4 iters
            int idx = tid + i * NTHREADS;
            int row = idx >> 5;        // 32 float4 per row
            int c4  = idx & 31;
            ((float4*)(sA + row * SSTR))[c4] = src[idx];
        }
    }
    // (visibility: __syncthreads inside first chunk of layer 1)

    const size_t pO = (size_t)p;
    layer_hid<OBS_D, true >(tid, W1 + pO * OBS_D * HID_D, b1 + pO * HID_D,
                            g1 + pO * HID_D, be1 + pO * HID_D,
                            sA, sB, sW0, sW1, sBias, sG, sBe);
    layer_hid<HID_D, true >(tid, W2 + pO * HID_D * HID_D, b2 + pO * HID_D,
                            g2 + pO * HID_D, be2 + pO * HID_D,
                            sB, sA, sW0, sW1, sBias, sG, sBe);
    layer_hid<HID_D, true >(tid, W3 + pO * HID_D * HID_D, b3 + pO * HID_D,
                            g3 + pO * HID_D, be3 + pO * HID_D,
                            sA, sB, sW0, sW1, sBias, sG, sBe);
    layer_out(tid, p, b0, W4 + pO * HID_D * ACT_D, b4 + pO * ACT_D,
              g4 + pO * ACT_D, be4 + pO * ACT_D,
              sB, sW0, sBias, sG, sBe, out);
}

extern "C" void kernel_launch(void* const* d_in, const int* in_sizes, int n_in,
                              void* d_out, int out_size)
{
    const float* obs = (const float*)d_in[0];
    const float* W1  = (const float*)d_in[1];
    const float* b1  = (const float*)d_in[2];
    const float* g1  = (const float*)d_in[3];
    const float* be1 = (const float*)d_in[4];
    const float* W2  = (const float*)d_in[5];
    const float* b2  = (const float*)d_in[6];
    const float* g2  = (const float*)d_in[7];
    const float* be2 = (const float*)d_in[8];
    const float* W3  = (const float*)d_in[9];
    const float* b3  = (const float*)d_in[10];
    const float* g3  = (const float*)d_in[11];
    const float* be3 = (const float*)d_in[12];
    const float* W4  = (const float*)d_in[13];
    const float* b4  = (const float*)d_in[14];
    const float* g4  = (const float*)d_in[15];
    const float* be4 = (const float*)d_in[16];
    float* out = (float*)d_out;

    const int smem_bytes =
        (2 * BT * SSTR + 2 * KC * HID_D + 3 * HID_D) * (int)sizeof(float);
    cudaFuncSetAttribute(mlp_fused_kernel,
                         cudaFuncAttributeMaxDynamicSharedMemorySize, smem_bytes);

    dim3 grid(NBATCH / BT, NPOL);   // 64 x 64 = 4096 CTAs
    mlp_fused_kernel<<<grid, NTHREADS, smem_bytes>>>(
        obs,
        W1, b1, g1, be1,
        W2, b2, g2, be2,
        W3, b3, g3, be3,
        W4, b4, g4, be4,
        out);
}

// round 10
// speedup vs baseline: 2.3982x; 2.1258x over previous
#include <cuda_runtime.h>
#include <cstdint>

#define OBS_D 128
#define HID_D 256
#define ACT_D 32
#define NPOL 64
#define NBATCH 4096
#define MT 128            // batch rows per CTA
#define NTHREADS 512
#define ASTR 260          // activation row stride (floats), === 4 mod 32
#define WSTR 36           // weight k-stride (floats) within a chunk, === 4 mod 32
#define CH_HID (HID_D * WSTR)   // 9216 u32 per hidden-layer weight chunk (36KB)
#define CH_OUT (ACT_D * WSTR)   // 1152 u32 per output-layer weight chunk (4.5KB)

// ---------------- device scratch: transposed, tf32-rounded, padded weights
// layout per (policy, chunk): [n][kl] with kl stride WSTR (kl<32 real, rest pad)
__device__ uint32_t gW1T[NPOL * 4 * CH_HID];
__device__ uint32_t gW2T[NPOL * 8 * CH_HID];
__device__ uint32_t gW3T[NPOL * 8 * CH_HID];
__device__ uint32_t gW4T[NPOL * 8 * CH_OUT];

// ---------------- helpers
__device__ __forceinline__ uint32_t f2tf32(float f) {
    uint32_t r; asm("cvt.rna.tf32.f32 %0, %1;" : "=r"(r) : "f"(f)); return r;
}
__device__ __forceinline__ void cp_commit() { asm volatile("cp.async.commit_group;"); }
__device__ __forceinline__ void cp_wait0()  { asm volatile("cp.async.wait_group 0;"); }
__device__ __forceinline__ void cp_wait1()  { asm volatile("cp.async.wait_group 1;"); }

__device__ __forceinline__ void cp_chunk(uint32_t* dst, const uint32_t* src, int units) {
    uint32_t d = (uint32_t)__cvta_generic_to_shared(dst);
    for (int u = threadIdx.x; u < units; u += NTHREADS)
        asm volatile("cp.async.cg.shared.global [%0], [%1], 16;"
                     :: "r"(d + (uint32_t)u * 16u), "l"(src + (size_t)u * 4) : "memory");
}

// m16n8k8 tf32 MMA, D += A*B (C==D registers)
__device__ __forceinline__ void mma8(float* d, uint32_t a0, uint32_t a1,
                                     uint32_t a2, uint32_t a3,
                                     uint32_t b0, uint32_t b1) {
    asm volatile(
        "mma.sync.aligned.m16n8k8.row.col.f32.tf32.tf32.f32 "
        "{%0,%1,%2,%3}, {%4,%5,%6,%7}, {%8,%9}, {%0,%1,%2,%3};\n"
        : "+f"(d[0]), "+f"(d[1]), "+f"(d[2]), "+f"(d[3])
        : "r"(a0), "r"(a1), "r"(a2), "r"(a3), "r"(b0), "r"(b1));
}

// ---------------- weight prepass: W[p][k][n] -> chunks [n][kl(36)] tf32
// block = (chunk ch, policy p); smem-staged for coalesced read AND write.
__global__ void prep_w(const float* __restrict__ W, int which, int DIN, int DOUT) {
    __shared__ float s[32 * 256];
    uint32_t* dst = which == 0 ? gW1T : which == 1 ? gW2T : which == 2 ? gW3T : gW4T;
    const int ch = blockIdx.x, p = blockIdx.y, NCH = DIN / 32;
    const float* src = W + ((size_t)p * DIN + (size_t)ch * 32) * DOUT;
    for (int i = threadIdx.x; i < 32 * DOUT; i += blockDim.x)
        s[i] = src[i];                        // s[k][n]
    __syncthreads();
    uint32_t* o = dst + ((size_t)p * NCH + ch) * ((size_t)DOUT * WSTR);
    for (int i = threadIdx.x; i < DOUT * WSTR; i += blockDim.x) {
        int n = i / WSTR, kl = i % WSTR;
        o[i] = (kl < 32) ? f2tf32(s[kl * DOUT + n]) : 0u;
    }
}

// ---------------- one hidden layer: acts[128,DIN] @ W[DIN,256] (+bias,GN,ELU?)
// acts live in sAct (tf32 bits, row stride ASTR); result written back in place.
template<int NCH>
__device__ __forceinline__ void layer_hidden(
    const uint32_t* wsrc, const uint32_t* nextw, int next_units,
    const float* __restrict__ bias, const float* __restrict__ gam,
    const float* __restrict__ bet,
    uint32_t* actu, uint32_t* wb0, uint32_t* wb1, float* sPar, float2* sRed,
    bool doAct)
{
    const int tid = threadIdx.x, lane = tid & 31, wid = tid >> 5;
    const int rg = wid & 3, wc = wid >> 2;
    const int r = lane >> 2, c = lane & 3;
    const int rowb = rg * 32 + r;

    if (tid < HID_D) {
        sPar[tid]       = bias[tid];
        sPar[256 + tid] = gam[tid];
        sPar[512 + tid] = bet[tid];
    }

    float acc[2][8][4];
#pragma unroll
    for (int t = 0; t < 2; t++)
#pragma unroll
        for (int j = 0; j < 8; j++)
#pragma unroll
            for (int q = 0; q < 4; q++) acc[t][j][q] = 0.f;

    for (int ch = 0; ch < NCH; ch++) {
        uint32_t* wcur = (ch & 1) ? wb1 : wb0;
        if (ch + 1 < NCH) {
            cp_chunk(((ch + 1) & 1) ? wb1 : wb0, wsrc + (size_t)(ch + 1) * CH_HID, CH_HID / 4);
            cp_commit();
            cp_wait1();
        } else {
            cp_wait0();
        }
        __syncthreads();
        const int kb = ch * 32;
#pragma unroll
        for (int ks = 0; ks < 4; ks++) {
            uint32_t a0[2], a1[2], a2[2], a3[2];
#pragma unroll
            for (int t = 0; t < 2; t++) {
                const uint32_t* pa = actu + (size_t)(rowb + 16 * t) * ASTR + kb + ks * 8 + c;
                a0[t] = pa[0];
                a2[t] = pa[4];
                a1[t] = pa[8 * ASTR];
                a3[t] = pa[8 * ASTR + 4];
            }
            const uint32_t* pb = wcur + (size_t)(wc * 64 + r) * WSTR + ks * 8 + c;
#pragma unroll
            for (int j = 0; j < 8; j++) {
                uint32_t b0 = pb[j * 8 * WSTR];
                uint32_t b1 = pb[j * 8 * WSTR + 4];
                mma8(acc[0][j], a0[0], a1[0], a2[0], a3[0], b0, b1);
                mma8(acc[1][j], a0[1], a1[1], a2[1], a3[1], b0, b1);
            }
        }
        __syncthreads();
    }

    // prefetch next layer's chunk 0 into wb0 (free: last chunk used wb1, NCH even)
    cp_chunk(wb0, nextw, next_units);
    cp_commit();

    // ---- epilogue: bias + GroupNorm(256) (+ELU) -> tf32 back into actu
    float s[4] = {0, 0, 0, 0}, s2[4] = {0, 0, 0, 0};
#pragma unroll
    for (int t = 0; t < 2; t++)
#pragma unroll
        for (int j = 0; j < 8; j++) {
            const int col = wc * 64 + j * 8 + 2 * c;
            float d0 = acc[t][j][0] + sPar[col];
            float d1 = acc[t][j][1] + sPar[col + 1];
            float d2 = acc[t][j][2] + sPar[col];
            float d3 = acc[t][j][3] + sPar[col + 1];
            acc[t][j][0] = d0; acc[t][j][1] = d1;
            acc[t][j][2] = d2; acc[t][j][3] = d3;
            s[2 * t]      += d0 + d1;  s2[2 * t]      += d0 * d0 + d1 * d1;
            s[2 * t + 1]  += d2 + d3;  s2[2 * t + 1]  += d2 * d2 + d3 * d3;
        }
#pragma unroll
    for (int q = 0; q < 4; q++) {
        s[q]  += __shfl_xor_sync(0xffffffffu, s[q], 1);
        s2[q] += __shfl_xor_sync(0xffffffffu, s2[q], 1);
        s[q]  += __shfl_xor_sync(0xffffffffu, s[q], 2);
        s2[q] += __shfl_xor_sync(0xffffffffu, s2[q], 2);
    }
    if (c == 0) {
#pragma unroll
        for (int t = 0; t < 2; t++)
#pragma unroll
            for (int h = 0; h < 2; h++)
                sRed[(rowb + 16 * t + 8 * h) * 4 + wc] =
                    make_float2(s[2 * t + h], s2[2 * t + h]);
    }
    __syncthreads();
    float mu[4], rs[4];
#pragma unroll
    for (int t = 0; t < 2; t++)
#pragma unroll
        for (int h = 0; h < 2; h++) {
            const int row = rowb + 16 * t + 8 * h;
            float2 p0 = sRed[row * 4 + 0], p1 = sRed[row * 4 + 1];
            float2 p2 = sRed[row * 4 + 2], p3 = sRed[row * 4 + 3];
            float S  = p0.x + p1.x + p2.x + p3.x;
            float S2 = p0.y + p1.y + p2.y + p3.y;
            float m  = S * (1.f / HID_D);
            float v  = fmaxf(S2 * (1.f / HID_D) - m * m, 0.f);
            mu[2 * t + h] = m;
            rs[2 * t + h] = rsqrtf(v + 1e-5f);
        }
#pragma unroll
    for (int t = 0; t < 2; t++)
#pragma unroll
        for (int j = 0; j < 8; j++) {
            const int col = wc * 64 + j * 8 + 2 * c;
            const float g0 = sPar[256 + col], g1 = sPar[256 + col + 1];
            const float e0 = sPar[512 + col], e1 = sPar[512 + col + 1];
#pragma unroll
            for (int h = 0; h < 2; h++) {
                const int q = 2 * t + h;
                float d0 = (acc[t][j][2 * h]     - mu[q]) * rs[q] * g0 + e0;
                float d1 = (acc[t][j][2 * h + 1] - mu[q]) * rs[q] * g1 + e1;
                if (doAct) {
                    d0 = (d0 > 0.f) ? d0 : expm1f(d0);
                    d1 = (d1 > 0.f) ? d1 : expm1f(d1);
                }
                uint2 u = make_uint2(f2tf32(d0), f2tf32(d1));
                *(uint2*)(actu + (size_t)(rowb + 16 * t + 8 * h) * ASTR + col) = u;
            }
        }
    __syncthreads();   // protect sPar/sRed before next layer rewrites them
}

// ---------------- final layer: acts[128,256] @ W4[256,32] + bias, GN(32) -> out
__device__ __forceinline__ void layer_out(
    const uint32_t* wsrc,
    const float* __restrict__ bias, const float* __restrict__ gam,
    const float* __restrict__ bet,
    uint32_t* actu, uint32_t* wb0, uint32_t* wb1, float* sPar, float2* sRed,
    float* __restrict__ out, int p, int b0)
{
    const int tid = threadIdx.x, lane = tid & 31, wid = tid >> 5;
    const int rg = wid & 3, wc = wid >> 2;
    const int r = lane >> 2, c = lane & 3;
    const int rowb = rg * 32 + r;

    if (tid < ACT_D) {
        sPar[tid]       = bias[tid];
        sPar[256 + tid] = gam[tid];
        sPar[512 + tid] = bet[tid];
    }

    float acc[2][4];
#pragma unroll
    for (int t = 0; t < 2; t++)
#pragma unroll
        for (int q = 0; q < 4; q++) acc[t][q] = 0.f;

    for (int ch = 0; ch < 8; ch++) {
        uint32_t* wcur = (ch & 1) ? wb1 : wb0;
        if (ch + 1 < 8) {
            cp_chunk(((ch + 1) & 1) ? wb1 : wb0, wsrc + (size_t)(ch + 1) * CH_OUT, CH_OUT / 4);
            cp_commit();
            cp_wait1();
        } else {
            cp_wait0();
        }
        __syncthreads();
        const int kb = ch * 32;
#pragma unroll
        for (int ks = 0; ks < 4; ks++) {
            uint32_t a0[2], a1[2], a2[2], a3[2];
#pragma unroll
            for (int t = 0; t < 2; t++) {
                const uint32_t* pa = actu + (size_t)(rowb + 16 * t) * ASTR + kb + ks * 8 + c;
                a0[t] = pa[0];
                a2[t] = pa[4];
                a1[t] = pa[8 * ASTR];
                a3[t] = pa[8 * ASTR + 4];
            }
            const uint32_t* pb = wcur + (size_t)(wc * 8 + r) * WSTR + ks * 8 + c;
            uint32_t b0 = pb[0], b1 = pb[4];
            mma8(acc[0], a0[0], a1[0], a2[0], a3[0], b0, b1);
            mma8(acc[1], a0[1], a1[1], a2[1], a3[1], b0, b1);
        }
        __syncthreads();
    }

    // ---- epilogue: bias + GN over 32 cols -> gmem fp32
    const int col = wc * 8 + 2 * c;
    float s[4], s2[4];
#pragma unroll
    for (int t = 0; t < 2; t++) {
        float d0 = acc[t][0] + sPar[col];
        float d1 = acc[t][1] + sPar[col + 1];
        float d2 = acc[t][2] + sPar[col];
        float d3 = acc[t][3] + sPar[col + 1];
        acc[t][0] = d0; acc[t][1] = d1; acc[t][2] = d2; acc[t][3] = d3;
        s[2 * t]     = d0 + d1;  s2[2 * t]     = d0 * d0 + d1 * d1;
        s[2 * t + 1] = d2 + d3;  s2[2 * t + 1] = d2 * d2 + d3 * d3;
    }
#pragma unroll
    for (int q = 0; q < 4; q++) {
        s[q]  += __shfl_xor_sync(0xffffffffu, s[q], 1);
        s2[q] += __shfl_xor_sync(0xffffffffu, s2[q], 1);
        s[q]  += __shfl_xor_sync(0xffffffffu, s[q], 2);
        s2[q] += __shfl_xor_sync(0xffffffffu, s2[q], 2);
    }
    if (c == 0) {
#pragma unroll
        for (int t = 0; t < 2; t++)
#pragma unroll
            for (int h = 0; h < 2; h++)
                sRed[(rowb + 16 * t + 8 * h) * 4 + wc] =
                    make_float2(s[2 * t + h], s2[2 * t + h]);
    }
    __syncthreads();
#pragma unroll
    for (int t = 0; t < 2; t++)
#pragma unroll
        for (int h = 0; h < 2; h++) {
            const int row = rowb + 16 * t + 8 * h;
            float2 p0 = sRed[row * 4 + 0], p1 = sRed[row * 4 + 1];
            float2 p2 = sRed[row * 4 + 2], p3 = sRed[row * 4 + 3];
            float S  = p0.x + p1.x + p2.x + p3.x;
            float S2 = p0.y + p1.y + p2.y + p3.y;
            float m  = S * (1.f / ACT_D);
            float v  = fmaxf(S2 * (1.f / ACT_D) - m * m, 0.f);
            float rstd = rsqrtf(v + 1e-5f);
            float2 o;
            o.x = (acc[t][2 * h]     - m) * rstd * sPar[256 + col]     + sPar[512 + col];
            o.y = (acc[t][2 * h + 1] - m) * rstd * sPar[256 + col + 1] + sPar[512 + col + 1];
            *(float2*)(out + (size_t)(b0 + row) * (NPOL * ACT_D) + (size_t)p * ACT_D + col) = o;
        }
}

// ---------------- main fused kernel: CTA = (policy, 128 batch rows)
__global__ void __launch_bounds__(NTHREADS, 1)
mlp_mma_kernel(const float* __restrict__ obs,
               const float* __restrict__ b1, const float* __restrict__ g1, const float* __restrict__ be1,
               const float* __restrict__ b2, const float* __restrict__ g2, const float* __restrict__ be2,
               const float* __restrict__ b3, const float* __restrict__ g3, const float* __restrict__ be3,
               const float* __restrict__ b4, const float* __restrict__ g4, const float* __restrict__ be4,
               float* __restrict__ out)
{
    extern __shared__ float smem[];
    float*    sAct = smem;                                    // 128*260 floats
    uint32_t* actu = (uint32_t*)sAct;
    uint32_t* wb0  = (uint32_t*)(sAct + MT * ASTR);           // CH_HID u32
    uint32_t* wb1  = wb0 + CH_HID;                            // CH_HID u32
    float*    sPar = (float*)(wb1 + CH_HID);                  // 768 floats
    float2*   sRed = (float2*)(sPar + 768);                   // 512 float2

    const int tid = threadIdx.x;
    const int p   = blockIdx.y;
    const int b0  = blockIdx.x * MT;
    const size_t pO = (size_t)p;

    // prefetch W1 chunk 0 immediately
    cp_chunk(wb0, gW1T + pO * 4 * CH_HID, CH_HID / 4);
    cp_commit();

    // stage observation tile [128,128] -> tf32 bits in sAct
    {
        const float4* src = (const float4*)(obs + (size_t)b0 * OBS_D);
#pragma unroll
        for (int i = 0; i < 8; i++) {
            int idx = tid + i * NTHREADS;      // 0..4095 float4s
            int row = idx >> 5, c4 = idx & 31;
            float4 v = src[idx];
            uint4 u = make_uint4(f2tf32(v.x), f2tf32(v.y), f2tf32(v.z), f2tf32(v.w));
            *(uint4*)(actu + (size_t)row * ASTR + c4 * 4) = u;
        }
    }
    // visibility: first __syncthreads inside layer_hidden's chunk loop

    layer_hidden<4>(gW1T + pO * 4 * CH_HID, gW2T + pO * 8 * CH_HID, CH_HID / 4,
                    b1 + pO * HID_D, g1 + pO * HID_D, be1 + pO * HID_D,
                    actu, wb0, wb1, sPar, sRed, true);
    layer_hidden<8>(gW2T + pO * 8 * CH_HID, gW3T + pO * 8 * CH_HID, CH_HID / 4,
                    b2 + pO * HID_D, g2 + pO * HID_D, be2 + pO * HID_D,
                    actu, wb0, wb1, sPar, sRed, true);
    layer_hidden<8>(gW3T + pO * 8 * CH_HID, gW4T + pO * 8 * CH_OUT, CH_OUT / 4,
                    b3 + pO * HID_D, g3 + pO * HID_D, be3 + pO * HID_D,
                    actu, wb0, wb1, sPar, sRed, true);
    layer_out(gW4T + pO * 8 * CH_OUT,
              b4 + pO * ACT_D, g4 + pO * ACT_D, be4 + pO * ACT_D,
              actu, wb0, wb1, sPar, sRed, out, p, b0);
}

// ---------------- launch
extern "C" void kernel_launch(void* const* d_in, const int* in_sizes, int n_in,
                              void* d_out, int out_size)
{
    const float* obs = (const float*)d_in[0];
    const float* W1  = (const float*)d_in[1];
    const float* b1  = (const float*)d_in[2];
    const float* g1  = (const float*)d_in[3];
    const float* be1 = (const float*)d_in[4];
    const float* W2  = (const float*)d_in[5];
    const float* b2  = (const float*)d_in[6];
    const float* g2  = (const float*)d_in[7];
    const float* be2 = (const float*)d_in[8];
    const float* W3  = (const float*)d_in[9];
    const float* b3  = (const float*)d_in[10];
    const float* g3  = (const float*)d_in[11];
    const float* be3 = (const float*)d_in[12];
    const float* W4  = (const float*)d_in[13];
    const float* b4  = (const float*)d_in[14];
    const float* g4  = (const float*)d_in[15];
    const float* be4 = (const float*)d_in[16];
    float* out = (float*)d_out;

    // weight prepass: transpose + tf32-round + pad into streaming chunks
    prep_w<<<dim3(4, NPOL), 256>>>(W1, 0, OBS_D, HID_D);
    prep_w<<<dim3(8, NPOL), 256>>>(W2, 1, HID_D, HID_D);
    prep_w<<<dim3(8, NPOL), 256>>>(W3, 2, HID_D, HID_D);
    prep_w<<<dim3(8, NPOL), 256>>>(W4, 3, HID_D, ACT_D);

    const int smem_bytes =
        (MT * ASTR) * 4 + 2 * CH_HID * 4 + 768 * 4 + 512 * 8;   // 214016 B
    cudaFuncSetAttribute(mlp_mma_kernel,
                         cudaFuncAttributeMaxDynamicSharedMemorySize, smem_bytes);

    dim3 grid(NBATCH / MT, NPOL);   // 32 x 64 = 2048 CTAs
    mlp_mma_kernel<<<grid, NTHREADS, smem_bytes>>>(
        obs,
        b1, g1, be1,
        b2, g2, be2,
        b3, g3, be3,
        b4, g4, be4,
        out);
}

// round 11
// speedup vs baseline: 2.9141x; 1.2151x over previous
#include <cuda_runtime.h>
#include <cstdint>

#define OBS_D 128
#define HID_D 256
#define ACT_D 32
#define NPOL 64
#define NBATCH 4096
#define MT 128            // batch rows per CTA
#define NTHREADS 512
#define ASTR 264          // activation row stride (u32), === 8 mod 32
#define WSTR 40           // weight n-row stride (u32), === 8 mod 32
#define CH_HID (HID_D * WSTR)   // 10240 u32 per hidden weight chunk (40KB)
#define CH_OUT (ACT_D * WSTR)   // 1280 u32 per output weight chunk (5KB)

// ---------------- device scratch: transposed, tf32, pair-interleaved weights
// per (policy, 32-K chunk): [n][kl(WSTR)]; within each 8-k group, position
// pos(k) = 2*(k&3) + ((k>>2)&1)  =>  (k, k+4) are adjacent (one LDS.64 = b0,b1)
__device__ uint32_t gW1T[NPOL * 4 * CH_HID];
__device__ uint32_t gW2T[NPOL * 8 * CH_HID];
__device__ uint32_t gW3T[NPOL * 8 * CH_HID];
__device__ uint32_t gW4T[NPOL * 8 * CH_OUT];

// ---------------- helpers
__device__ __forceinline__ uint32_t f2tf32(float f) {
    uint32_t r; asm("cvt.rna.tf32.f32 %0, %1;" : "=r"(r) : "f"(f)); return r;
}
__device__ __forceinline__ void cp_commit() { asm volatile("cp.async.commit_group;"); }
__device__ __forceinline__ void cp_wait0()  { asm volatile("cp.async.wait_group 0;"); }
__device__ __forceinline__ void cp_wait1()  { asm volatile("cp.async.wait_group 1;"); }

__device__ __forceinline__ void cp_chunk(uint32_t* dst, const uint32_t* src, int units) {
    uint32_t d = (uint32_t)__cvta_generic_to_shared(dst);
    for (int u = threadIdx.x; u < units; u += NTHREADS)
        asm volatile("cp.async.cg.shared.global [%0], [%1], 16;"
                     :: "r"(d + (uint32_t)u * 16u), "l"(src + (size_t)u * 4) : "memory");
}

// m16n8k8 tf32 MMA, D += A*B
__device__ __forceinline__ void mma8(float* d, uint32_t a0, uint32_t a1,
                                     uint32_t a2, uint32_t a3,
                                     uint32_t b0, uint32_t b1) {
    asm volatile(
        "mma.sync.aligned.m16n8k8.row.col.f32.tf32.tf32.f32 "
        "{%0,%1,%2,%3}, {%4,%5,%6,%7}, {%8,%9}, {%0,%1,%2,%3};\n"
        : "+f"(d[0]), "+f"(d[1]), "+f"(d[2]), "+f"(d[3])
        : "r"(a0), "r"(a1), "r"(a2), "r"(a3), "r"(b0), "r"(b1));
}

__device__ __forceinline__ float elu(float x) {
    return (x > 0.f) ? x : (__expf(x) - 1.f);
}

// ---------------- single merged weight prepass
// block = flat chunk id over all 4 weights; smem-staged transpose + tf32 + perm
__global__ void prep_all(const float* __restrict__ W1, const float* __restrict__ W2,
                         const float* __restrict__ W3, const float* __restrict__ W4) {
    __shared__ float s[32 * 256];
    int b = blockIdx.x;
    const float* W; uint32_t* dst; int DOUT, NCH;
    if (b < 256)       { W = W1; dst = gW1T; DOUT = HID_D; NCH = 4; }
    else if (b < 768)  { W = W2; dst = gW2T; DOUT = HID_D; NCH = 8; b -= 256; }
    else if (b < 1280) { W = W3; dst = gW3T; DOUT = HID_D; NCH = 8; b -= 768; }
    else               { W = W4; dst = gW4T; DOUT = ACT_D; NCH = 8; b -= 1280; }
    const int p = b / NCH, ch = b % NCH;
    const int DIN = NCH * 32;
    const float* src = W + ((size_t)p * DIN + (size_t)ch * 32) * DOUT;
    for (int i = threadIdx.x; i < 32 * DOUT; i += blockDim.x)
        s[i] = src[i];                       // s[k_local][n]
    __syncthreads();
    uint32_t* o = dst + ((size_t)p * NCH + ch) * ((size_t)DOUT * WSTR);
    for (int i = threadIdx.x; i < DOUT * WSTR; i += blockDim.x) {
        int n = i / WSTR, kl = i % WSTR;
        uint32_t v = 0;
        if (kl < 32) {
            int within = kl & 7;             // inverse of pos(k)
            int k = (kl & ~7) + ((within & 1) << 2) + (within >> 1);
            v = f2tf32(s[k * DOUT + n]);
        }
        o[i] = v;
    }
}

// ---------------- one hidden layer: acts[128,DIN] @ W[DIN,256] (+bias,GN,ELU)
template<int NCH>
__device__ __forceinline__ void layer_hidden(
    const uint32_t* wsrc, const uint32_t* nextw, int next_units,
    const float* __restrict__ bias, const float* __restrict__ gam,
    const float* __restrict__ bet,
    uint32_t* actu, uint32_t* wb0, uint32_t* wb1, float* sPar, float2* sRed)
{
    const int tid = threadIdx.x, lane = tid & 31, wid = tid >> 5;
    const int rg = wid & 3, wc = wid >> 2;
    const int r = lane >> 2, c = lane & 3;
    const int rowb = rg * 32 + r;
    const int ep0 = ((2 * c) & 3) * 2 + ((c >> 1) & 1);   // perm pos of col (even)

    if (tid < HID_D) {
        sPar[tid]       = bias[tid];
        sPar[256 + tid] = gam[tid];
        sPar[512 + tid] = bet[tid];
    }

    float acc[2][8][4];
#pragma unroll
    for (int t = 0; t < 2; t++)
#pragma unroll
        for (int j = 0; j < 8; j++)
#pragma unroll
            for (int q = 0; q < 4; q++) acc[t][j][q] = 0.f;

    for (int ch = 0; ch < NCH; ch++) {
        const uint32_t* wcur = (ch & 1) ? wb1 : wb0;
        if (ch + 1 < NCH) {
            cp_chunk(((ch + 1) & 1) ? wb1 : wb0, wsrc + (size_t)(ch + 1) * CH_HID, CH_HID / 4);
            cp_commit();
            cp_wait1();
        } else {
            cp_wait0();
        }
        __syncthreads();
        const int kb = ch * 32;
#pragma unroll
        for (int ks = 0; ks < 4; ks++) {
            uint2 alo[2], ahi[2];
#pragma unroll
            for (int t = 0; t < 2; t++) {
                const uint32_t* pa = actu + (size_t)(rowb + 16 * t) * ASTR + kb + ks * 8 + 2 * c;
                alo[t] = *(const uint2*)pa;                // a0 (k=c), a2 (k=c+4)
                ahi[t] = *(const uint2*)(pa + 8 * ASTR);   // a1, a3
            }
            const uint32_t* pb = wcur + (size_t)(wc * 64 + r) * WSTR + ks * 8 + 2 * c;
#pragma unroll
            for (int j = 0; j < 8; j++) {
                uint2 bb = *(const uint2*)(pb + j * 8 * WSTR);   // b0 (k=c), b1 (k=c+4)
                mma8(acc[0][j], alo[0].x, ahi[0].x, alo[0].y, ahi[0].y, bb.x, bb.y);
                mma8(acc[1][j], alo[1].x, ahi[1].x, alo[1].y, ahi[1].y, bb.x, bb.y);
            }
        }
        __syncthreads();   // protect wcur from next iteration's cp.async
    }

    // prefetch next layer's chunk 0 into wb0 (last chunk used wb1; NCH even)
    cp_chunk(wb0, nextw, next_units);
    cp_commit();

    // ---- epilogue: bias + GroupNorm(256) + ELU -> tf32 (perm layout) in actu
    float s[4] = {0, 0, 0, 0}, s2[4] = {0, 0, 0, 0};
#pragma unroll
    for (int t = 0; t < 2; t++)
#pragma unroll
        for (int j = 0; j < 8; j++) {
            const int col = wc * 64 + j * 8 + 2 * c;
            float d0 = acc[t][j][0] + sPar[col];
            float d1 = acc[t][j][1] + sPar[col + 1];
            float d2 = acc[t][j][2] + sPar[col];
            float d3 = acc[t][j][3] + sPar[col + 1];
            acc[t][j][0] = d0; acc[t][j][1] = d1;
            acc[t][j][2] = d2; acc[t][j][3] = d3;
            s[2 * t]     += d0 + d1;  s2[2 * t]     += d0 * d0 + d1 * d1;
            s[2 * t + 1] += d2 + d3;  s2[2 * t + 1] += d2 * d2 + d3 * d3;
        }
#pragma unroll
    for (int q = 0; q < 4; q++) {
        s[q]  += __shfl_xor_sync(0xffffffffu, s[q], 1);
        s2[q] += __shfl_xor_sync(0xffffffffu, s2[q], 1);
        s[q]  += __shfl_xor_sync(0xffffffffu, s[q], 2);
        s2[q] += __shfl_xor_sync(0xffffffffu, s2[q], 2);
    }
    if (c == 0) {
#pragma unroll
        for (int t = 0; t < 2; t++)
#pragma unroll
            for (int h = 0; h < 2; h++)
                sRed[(rowb + 16 * t + 8 * h) * 4 + wc] =
                    make_float2(s[2 * t + h], s2[2 * t + h]);
    }
    __syncthreads();
    float mu[4], rs[4];
#pragma unroll
    for (int t = 0; t < 2; t++)
#pragma unroll
        for (int h = 0; h < 2; h++) {
            const int row = rowb + 16 * t + 8 * h;
            float2 p0 = sRed[row * 4 + 0], p1 = sRed[row * 4 + 1];
            float2 p2 = sRed[row * 4 + 2], p3 = sRed[row * 4 + 3];
            float S  = p0.x + p1.x + p2.x + p3.x;
            float S2 = p0.y + p1.y + p2.y + p3.y;
            float m  = S * (1.f / HID_D);
            float v  = fmaxf(S2 * (1.f / HID_D) - m * m, 0.f);
            mu[2 * t + h] = m;
            rs[2 * t + h] = rsqrtf(v + 1e-5f);
        }
#pragma unroll
    for (int t = 0; t < 2; t++)
#pragma unroll
        for (int j = 0; j < 8; j++) {
            const int col = wc * 64 + j * 8 + 2 * c;
            const float g0 = sPar[256 + col], g1 = sPar[256 + col + 1];
            const float e0 = sPar[512 + col], e1 = sPar[512 + col + 1];
#pragma unroll
            for (int h = 0; h < 2; h++) {
                const int q = 2 * t + h;
                float d0 = elu((acc[t][j][2 * h]     - mu[q]) * rs[q] * g0 + e0);
                float d1 = elu((acc[t][j][2 * h + 1] - mu[q]) * rs[q] * g1 + e1);
                uint32_t* dst = actu + (size_t)(rowb + 16 * t + 8 * h) * ASTR
                              + wc * 64 + j * 8;
                dst[ep0]     = f2tf32(d0);     // perm pos of col
                dst[ep0 + 2] = f2tf32(d1);     // perm pos of col+1
            }
        }
    __syncthreads();
}

// ---------------- final layer: acts[128,256] @ W4[256,32] + bias, GN(32) -> out
__device__ __forceinline__ void layer_out(
    const uint32_t* wsrc,
    const float* __restrict__ bias, const float* __restrict__ gam,
    const float* __restrict__ bet,
    uint32_t* actu, uint32_t* wb0, uint32_t* wb1, float* sPar, float2* sRed,
    float* __restrict__ out, int p, int b0)
{
    const int tid = threadIdx.x, lane = tid & 31, wid = tid >> 5;
    const int rg = wid & 3, wc = wid >> 2;
    const int r = lane >> 2, c = lane & 3;
    const int rowb = rg * 32 + r;

    if (tid < ACT_D) {
        sPar[tid]       = bias[tid];
        sPar[256 + tid] = gam[tid];
        sPar[512 + tid] = bet[tid];
    }

    float acc[2][4];
#pragma unroll
    for (int t = 0; t < 2; t++)
#pragma unroll
        for (int q = 0; q < 4; q++) acc[t][q] = 0.f;

    for (int ch = 0; ch < 8; ch++) {
        const uint32_t* wcur = (ch & 1) ? wb1 : wb0;
        if (ch + 1 < 8) {
            cp_chunk(((ch + 1) & 1) ? wb1 : wb0, wsrc + (size_t)(ch + 1) * CH_OUT, CH_OUT / 4);
            cp_commit();
            cp_wait1();
        } else {
            cp_wait0();
        }
        __syncthreads();
        const int kb = ch * 32;
#pragma unroll
        for (int ks = 0; ks < 4; ks++) {
            uint2 alo[2], ahi[2];
#pragma unroll
            for (int t = 0; t < 2; t++) {
                const uint32_t* pa = actu + (size_t)(rowb + 16 * t) * ASTR + kb + ks * 8 + 2 * c;
                alo[t] = *(const uint2*)pa;
                ahi[t] = *(const uint2*)(pa + 8 * ASTR);
            }
            uint2 bb = *(const uint2*)(wcur + (size_t)(wc * 8 + r) * WSTR + ks * 8 + 2 * c);
            mma8(acc[0], alo[0].x, ahi[0].x, alo[0].y, ahi[0].y, bb.x, bb.y);
            mma8(acc[1], alo[1].x, ahi[1].x, alo[1].y, ahi[1].y, bb.x, bb.y);
        }
        __syncthreads();
    }

    // ---- epilogue: bias + GN over 32 cols -> gmem fp32 (true col order)
    const int col = wc * 8 + 2 * c;
    float s[4], s2[4];
#pragma unroll
    for (int t = 0; t < 2; t++) {
        float d0 = acc[t][0] + sPar[col];
        float d1 = acc[t][1] + sPar[col + 1];
        float d2 = acc[t][2] + sPar[col];
        float d3 = acc[t][3] + sPar[col + 1];
        acc[t][0] = d0; acc[t][1] = d1; acc[t][2] = d2; acc[t][3] = d3;
        s[2 * t]     = d0 + d1;  s2[2 * t]     = d0 * d0 + d1 * d1;
        s[2 * t + 1] = d2 + d3;  s2[2 * t + 1] = d2 * d2 + d3 * d3;
    }
#pragma unroll
    for (int q = 0; q < 4; q++) {
        s[q]  += __shfl_xor_sync(0xffffffffu, s[q], 1);
        s2[q] += __shfl_xor_sync(0xffffffffu, s2[q], 1);
        s[q]  += __shfl_xor_sync(0xffffffffu, s[q], 2);
        s2[q] += __shfl_xor_sync(0xffffffffu, s2[q], 2);
    }
    if (c == 0) {
#pragma unroll
        for (int t = 0; t < 2; t++)
#pragma unroll
            for (int h = 0; h < 2; h++)
                sRed[(rowb + 16 * t + 8 * h) * 4 + wc] =
                    make_float2(s[2 * t + h], s2[2 * t + h]);
    }
    __syncthreads();
#pragma unroll
    for (int t = 0; t < 2; t++)
#pragma unroll
        for (int h = 0; h < 2; h++) {
            const int row = rowb + 16 * t + 8 * h;
            float2 p0 = sRed[row * 4 + 0], p1 = sRed[row * 4 + 1];
            float2 p2 = sRed[row * 4 + 2], p3 = sRed[row * 4 + 3];
            float S  = p0.x + p1.x + p2.x + p3.x;
            float S2 = p0.y + p1.y + p2.y + p3.y;
            float m  = S * (1.f / ACT_D);
            float v  = fmaxf(S2 * (1.f / ACT_D) - m * m, 0.f);
            float rstd = rsqrtf(v + 1e-5f);
            float2 o;
            o.x = (acc[t][2 * h]     - m) * rstd * sPar[256 + col]     + sPar[512 + col];
            o.y = (acc[t][2 * h + 1] - m) * rstd * sPar[256 + col + 1] + sPar[512 + col + 1];
            *(float2*)(out + (size_t)(b0 + row) * (NPOL * ACT_D) + (size_t)p * ACT_D + col) = o;
        }
}

// ---------------- main fused kernel: CTA = (policy, 128 batch rows)
__global__ void __launch_bounds__(NTHREADS, 1)
mlp_mma_kernel(const float* __restrict__ obs,
               const float* __restrict__ b1, const float* __restrict__ g1, const float* __restrict__ be1,
               const float* __restrict__ b2, const float* __restrict__ g2, const float* __restrict__ be2,
               const float* __restrict__ b3, const float* __restrict__ g3, const float* __restrict__ be3,
               const float* __restrict__ b4, const float* __restrict__ g4, const float* __restrict__ be4,
               float* __restrict__ out)
{
    extern __shared__ float smem[];
    uint32_t* actu = (uint32_t*)smem;                         // MT*ASTR u32
    uint32_t* wb0  = actu + (size_t)MT * ASTR;                // CH_HID u32
    uint32_t* wb1  = wb0 + CH_HID;                            // CH_HID u32
    float*    sPar = (float*)(wb1 + CH_HID);                  // 768 floats
    float2*   sRed = (float2*)(sPar + 768);                   // 512 float2

    const int tid = threadIdx.x;
    const int p   = blockIdx.y;
    const int b0  = blockIdx.x * MT;
    const size_t pO = (size_t)p;

    // prefetch W1 chunk 0 immediately
    cp_chunk(wb0, gW1T + pO * 4 * CH_HID, CH_HID / 4);
    cp_commit();

    // stage observation tile [128,128] -> tf32 bits, pair-perm layout
    for (int i = tid; i < MT * (OBS_D / 8); i += NTHREADS) {
        int row = i >> 4, g = i & 15;
        const float4* srow = (const float4*)(obs + (size_t)(b0 + row) * OBS_D + g * 8);
        float4 v0 = srow[0], v1 = srow[1];
        uint32_t* d = actu + (size_t)row * ASTR + g * 8;
        *(uint2*)(d + 0) = make_uint2(f2tf32(v0.x), f2tf32(v1.x));   // k, k+4
        *(uint2*)(d + 2) = make_uint2(f2tf32(v0.y), f2tf32(v1.y));
        *(uint2*)(d + 4) = make_uint2(f2tf32(v0.z), f2tf32(v1.z));
        *(uint2*)(d + 6) = make_uint2(f2tf32(v0.w), f2tf32(v1.w));
    }
    // visibility: first __syncthreads inside layer_hidden's chunk loop

    layer_hidden<4>(gW1T + pO * 4 * CH_HID, gW2T + pO * 8 * CH_HID, CH_HID / 4,
                    b1 + pO * HID_D, g1 + pO * HID_D, be1 + pO * HID_D,
                    actu, wb0, wb1, sPar, sRed);
    layer_hidden<8>(gW2T + pO * 8 * CH_HID, gW3T + pO * 8 * CH_HID, CH_HID / 4,
                    b2 + pO * HID_D, g2 + pO * HID_D, be2 + pO * HID_D,
                    actu, wb0, wb1, sPar, sRed);
    layer_hidden<8>(gW3T + pO * 8 * CH_HID, gW4T + pO * 8 * CH_OUT, CH_OUT / 4,
                    b3 + pO * HID_D, g3 + pO * HID_D, be3 + pO * HID_D,
                    actu, wb0, wb1, sPar, sRed);
    layer_out(gW4T + pO * 8 * CH_OUT,
              b4 + pO * ACT_D, g4 + pO * ACT_D, be4 + pO * ACT_D,
              actu, wb0, wb1, sPar, sRed, out, p, b0);
}

// ---------------- launch
extern "C" void kernel_launch(void* const* d_in, const int* in_sizes, int n_in,
                              void* d_out, int out_size)
{
    const float* obs = (const float*)d_in[0];
    const float* W1  = (const float*)d_in[1];
    const float* b1  = (const float*)d_in[2];
    const float* g1  = (const float*)d_in[3];
    const float* be1 = (const float*)d_in[4];
    const float* W2  = (const float*)d_in[5];
    const float* b2  = (const float*)d_in[6];
    const float* g2  = (const float*)d_in[7];
    const float* be2 = (const float*)d_in[8];
    const float* W3  = (const float*)d_in[9];
    const float* b3  = (const float*)d_in[10];
    const float* g3  = (const float*)d_in[11];
    const float* be3 = (const float*)d_in[12];
    const float* W4  = (const float*)d_in[13];
    const float* b4  = (const float*)d_in[14];
    const float* g4  = (const float*)d_in[15];
    const float* be4 = (const float*)d_in[16];
    float* out = (float*)d_out;

    // single merged prepass: 256 + 512 + 512 + 512 = 1792 chunk-blocks
    prep_all<<<1792, 256>>>(W1, W2, W3, W4);

    const int smem_bytes =
        (MT * ASTR) * 4 + 2 * CH_HID * 4 + 768 * 4 + 512 * 8;   // 224256 B
    cudaFuncSetAttribute(mlp_mma_kernel,
                         cudaFuncAttributeMaxDynamicSharedMemorySize, smem_bytes);

    dim3 grid(NBATCH / MT, NPOL);   // 32 x 64 = 2048 CTAs
    mlp_mma_kernel<<<grid, NTHREADS, smem_bytes>>>(
        obs,
        b1, g1, be1,
        b2, g2, be2,
        b3, g3, be3,
        b4, g4, be4,
        out);
}

// round 12
// speedup vs baseline: 3.3831x; 1.1609x over previous
#include <cuda_runtime.h>
#include <cstdint>

#define OBS_D 128
#define HID_D 256
#define ACT_D 32
#define NPOL 64
#define NBATCH 4096
#define MT 128            // batch rows per CTA
#define NTHREADS 512
#define PSTR 528          // activation pair-row stride (u32), === 16 mod 32
#define WPSTR 80          // weight pair-row stride (u32), === 16 mod 32
#define WSTR 40           // layer-4 weight n-row stride (old format)
#define CH_HID (128 * WPSTR)    // 10240 u32 per hidden weight chunk (40KB)
#define CH_OUT (ACT_D * WSTR)   // 1280 u32 per output weight chunk (5KB)

// ---------------- device scratch: transposed tf32 weights, HMMA-fragment-ordered
// hidden layers: per (policy, 32-K chunk): 128 pair-rows (n, n+8) x WPSTR;
//   block at (NP, oct, c): [W(n,k), W(n,k+4), W(n+8,k), W(n+8,k+4)], k=oct*8+c
// layer 4: old pair-k format: [n][kl(WSTR)], pos(k)=2*(k&3)+((k>>2)&1)
__device__ uint32_t gW1T[NPOL * 4 * CH_HID];
__device__ uint32_t gW2T[NPOL * 8 * CH_HID];
__device__ uint32_t gW3T[NPOL * 8 * CH_HID];
__device__ uint32_t gW4T[NPOL * 8 * CH_OUT];

// ---------------- helpers
__device__ __forceinline__ uint32_t f2tf32(float f) {
    uint32_t r; asm("cvt.rna.tf32.f32 %0, %1;" : "=r"(r) : "f"(f)); return r;
}
__device__ __forceinline__ void cp_commit() { asm volatile("cp.async.commit_group;"); }
__device__ __forceinline__ void cp_wait0()  { asm volatile("cp.async.wait_group 0;"); }
__device__ __forceinline__ void cp_wait1()  { asm volatile("cp.async.wait_group 1;"); }

__device__ __forceinline__ void cp_chunk(uint32_t* dst, const uint32_t* src, int units) {
    uint32_t d = (uint32_t)__cvta_generic_to_shared(dst);
    for (int u = threadIdx.x; u < units; u += NTHREADS)
        asm volatile("cp.async.cg.shared.global [%0], [%1], 16;"
                     :: "r"(d + (uint32_t)u * 16u), "l"(src + (size_t)u * 4) : "memory");
}

// m16n8k8 tf32 MMA, D += A*B. A quad arrives pre-ordered (one LDS.128).
__device__ __forceinline__ void mma8(float* d, uint32_t a0, uint32_t a1,
                                     uint32_t a2, uint32_t a3,
                                     uint32_t b0, uint32_t b1) {
    asm volatile(
        "mma.sync.aligned.m16n8k8.row.col.f32.tf32.tf32.f32 "
        "{%0,%1,%2,%3}, {%4,%5,%6,%7}, {%8,%9}, {%0,%1,%2,%3};\n"
        : "+f"(d[0]), "+f"(d[1]), "+f"(d[2]), "+f"(d[3])
        : "r"(a0), "r"(a1), "r"(a2), "r"(a3), "r"(b0), "r"(b1));
}

__device__ __forceinline__ float elu(float x) {
    return (x > 0.f) ? x : (__expf(x) - 1.f);
}

// ---------------- merged weight prepass
__global__ void prep_all(const float* __restrict__ W1, const float* __restrict__ W2,
                         const float* __restrict__ W3, const float* __restrict__ W4) {
    __shared__ float s[32 * 256];
    int b = blockIdx.x;
    const float* W; uint32_t* dst; int DOUT, NCH, fmt;
    if (b < 256)       { W = W1; dst = gW1T; DOUT = HID_D; NCH = 4; fmt = 0; }
    else if (b < 768)  { W = W2; dst = gW2T; DOUT = HID_D; NCH = 8; fmt = 0; b -= 256; }
    else if (b < 1280) { W = W3; dst = gW3T; DOUT = HID_D; NCH = 8; fmt = 0; b -= 768; }
    else               { W = W4; dst = gW4T; DOUT = ACT_D; NCH = 8; fmt = 1; b -= 1280; }
    const int p = b / NCH, ch = b % NCH;
    const int DIN = NCH * 32;
    const float* src = W + ((size_t)p * DIN + (size_t)ch * 32) * DOUT;
    for (int i = threadIdx.x; i < 32 * DOUT; i += blockDim.x)
        s[i] = src[i];                       // s[k_local][n]
    __syncthreads();
    if (fmt == 0) {
        // hidden: 128 pair-rows x WPSTR
        uint32_t* o = dst + ((size_t)p * NCH + ch) * CH_HID;
        for (int i = threadIdx.x; i < 128 * WPSTR; i += blockDim.x) {
            int NP = i / WPSTR, q = i % WPSTR;
            uint32_t v = 0;
            if (q < 64) {
                int oct = q >> 4, rem = q & 15, c4 = rem >> 2, pos = rem & 3;
                int wcc = NP >> 5, jj = (NP >> 3) & 3, rr = NP & 7;
                int n  = wcc * 64 + jj * 16 + rr + (pos >> 1) * 8;
                int kl = oct * 8 + c4 + (pos & 1) * 4;
                v = f2tf32(s[kl * DOUT + n]);
            }
            o[i] = v;
        }
    } else {
        // layer 4: old pair-k format
        uint32_t* o = dst + ((size_t)p * NCH + ch) * CH_OUT;
        for (int i = threadIdx.x; i < DOUT * WSTR; i += blockDim.x) {
            int n = i / WSTR, kl = i % WSTR;
            uint32_t v = 0;
            if (kl < 32) {
                int within = kl & 7;
                int k = (kl & ~7) + ((within & 1) << 2) + (within >> 1);
                v = f2tf32(s[k * DOUT + n]);
            }
            o[i] = v;
        }
    }
}

// ---------------- one hidden layer: acts[128,DIN] @ W[DIN,256] (+bias,GN,ELU)
template<int NCH>
__device__ __forceinline__ void layer_hidden(
    const uint32_t* wsrc, const uint32_t* nextw, int next_units,
    const float* __restrict__ bias, const float* __restrict__ gam,
    const float* __restrict__ bet,
    uint32_t* actu, uint32_t* wb0, uint32_t* wb1, float* sPar, float2* sRed)
{
    const int tid = threadIdx.x, lane = tid & 31, wid = tid >> 5;
    const int rg = wid & 3, wc = wid >> 2;
    const int r = lane >> 2, c = lane & 3;
    const int rowb = rg * 32 + r;

    if (tid < HID_D) {
        sPar[tid]       = bias[tid];
        sPar[256 + tid] = gam[tid];
        sPar[512 + tid] = bet[tid];
    }

    const uint32_t* aB0 = actu + (size_t)(rg * 16 + r) * PSTR + c * 4;  // t=0 pair-row
    const uint32_t* aB1 = aB0 + 8 * PSTR;                               // t=1 pair-row

    float acc[2][8][4];
#pragma unroll
    for (int t = 0; t < 2; t++)
#pragma unroll
        for (int j = 0; j < 8; j++)
#pragma unroll
            for (int q = 0; q < 4; q++) acc[t][j][q] = 0.f;

    for (int ch = 0; ch < NCH; ch++) {
        const uint32_t* wcur = (ch & 1) ? wb1 : wb0;
        if (ch + 1 < NCH) {
            cp_chunk(((ch + 1) & 1) ? wb1 : wb0, wsrc + (size_t)(ch + 1) * CH_HID, CH_HID / 4);
            cp_commit();
            cp_wait1();
        } else {
            cp_wait0();
        }
        __syncthreads();
        const uint32_t* pbB = wcur + (size_t)(wc * 32 + r) * WPSTR + c * 4;
#pragma unroll
        for (int ks = 0; ks < 4; ks++) {
            uint4 a0 = *(const uint4*)(aB0 + (ch * 4 + ks) * 16);
            uint4 a1 = *(const uint4*)(aB1 + (ch * 4 + ks) * 16);
#pragma unroll
            for (int jj = 0; jj < 4; jj++) {
                uint4 bb = *(const uint4*)(pbB + ks * 16 + jj * 8 * WPSTR);
                mma8(acc[0][2 * jj],     a0.x, a0.y, a0.z, a0.w, bb.x, bb.y);
                mma8(acc[0][2 * jj + 1], a0.x, a0.y, a0.z, a0.w, bb.z, bb.w);
                mma8(acc[1][2 * jj],     a1.x, a1.y, a1.z, a1.w, bb.x, bb.y);
                mma8(acc[1][2 * jj + 1], a1.x, a1.y, a1.z, a1.w, bb.z, bb.w);
            }
        }
        __syncthreads();   // protect wcur from next iteration's cp.async
    }

    // prefetch next layer's chunk 0 into wb0 (last chunk used wb1; NCH even)
    cp_chunk(wb0, nextw, next_units);
    cp_commit();

    // ---- epilogue: bias + GroupNorm(256) + ELU -> tf32, HMMA-ordered layout
    float s[4] = {0, 0, 0, 0}, s2[4] = {0, 0, 0, 0};
#pragma unroll
    for (int t = 0; t < 2; t++)
#pragma unroll
        for (int j = 0; j < 8; j++) {
            const int col = wc * 64 + j * 8 + 2 * c;
            float d0 = acc[t][j][0] + sPar[col];
            float d1 = acc[t][j][1] + sPar[col + 1];
            float d2 = acc[t][j][2] + sPar[col];
            float d3 = acc[t][j][3] + sPar[col + 1];
            acc[t][j][0] = d0; acc[t][j][1] = d1;
            acc[t][j][2] = d2; acc[t][j][3] = d3;
            s[2 * t]     += d0 + d1;  s2[2 * t]     += d0 * d0 + d1 * d1;
            s[2 * t + 1] += d2 + d3;  s2[2 * t + 1] += d2 * d2 + d3 * d3;
        }
#pragma unroll
    for (int q = 0; q < 4; q++) {
        s[q]  += __shfl_xor_sync(0xffffffffu, s[q], 1);
        s2[q] += __shfl_xor_sync(0xffffffffu, s2[q], 1);
        s[q]  += __shfl_xor_sync(0xffffffffu, s[q], 2);
        s2[q] += __shfl_xor_sync(0xffffffffu, s2[q], 2);
    }
    if (c == 0) {
#pragma unroll
        for (int t = 0; t < 2; t++)
#pragma unroll
            for (int h = 0; h < 2; h++)
                sRed[(rowb + 16 * t + 8 * h) * 4 + wc] =
                    make_float2(s[2 * t + h], s2[2 * t + h]);
    }
    __syncthreads();
    float mu[4], rs[4];
#pragma unroll
    for (int t = 0; t < 2; t++)
#pragma unroll
        for (int h = 0; h < 2; h++) {
            const int row = rowb + 16 * t + 8 * h;
            float2 p0 = sRed[row * 4 + 0], p1 = sRed[row * 4 + 1];
            float2 p2 = sRed[row * 4 + 2], p3 = sRed[row * 4 + 3];
            float S  = p0.x + p1.x + p2.x + p3.x;
            float S2 = p0.y + p1.y + p2.y + p3.y;
            float m  = S * (1.f / HID_D);
            float v  = fmaxf(S2 * (1.f / HID_D) - m * m, 0.f);
            mu[2 * t + h] = m;
            rs[2 * t + h] = rsqrtf(v + 1e-5f);
        }
    const int offE = ((2 * c) & 3) * 4 + (c >> 1) * 2;
    const int offO = ((2 * c + 1) & 3) * 4 + (c >> 1) * 2;
#pragma unroll
    for (int t = 0; t < 2; t++) {
        uint32_t* dbase = actu + (size_t)(rg * 16 + t * 8 + r) * PSTR + wc * 128;
#pragma unroll
        for (int j = 0; j < 8; j++) {
            const int col = wc * 64 + j * 8 + 2 * c;
            const float g0 = sPar[256 + col], e0 = sPar[512 + col];
            const float g1 = sPar[256 + col + 1], e1 = sPar[512 + col + 1];
            float v00 = elu((acc[t][j][0] - mu[2 * t])     * rs[2 * t]     * g0 + e0);
            float v01 = elu((acc[t][j][1] - mu[2 * t])     * rs[2 * t]     * g1 + e1);
            float v10 = elu((acc[t][j][2] - mu[2 * t + 1]) * rs[2 * t + 1] * g0 + e0);
            float v11 = elu((acc[t][j][3] - mu[2 * t + 1]) * rs[2 * t + 1] * g1 + e1);
            uint32_t* dst = dbase + j * 16;
            *(uint2*)(dst + offE) = make_uint2(f2tf32(v00), f2tf32(v10));
            *(uint2*)(dst + offO) = make_uint2(f2tf32(v01), f2tf32(v11));
        }
    }
    __syncthreads();
}

// ---------------- final layer: acts[128,256] @ W4[256,32] + bias, GN(32) -> out
__device__ __forceinline__ void layer_out(
    const uint32_t* wsrc,
    const float* __restrict__ bias, const float* __restrict__ gam,
    const float* __restrict__ bet,
    uint32_t* actu, uint32_t* wb0, uint32_t* wb1, float* sPar, float2* sRed,
    float* __restrict__ out, int p, int b0)
{
    const int tid = threadIdx.x, lane = tid & 31, wid = tid >> 5;
    const int rg = wid & 3, wc = wid >> 2;
    const int r = lane >> 2, c = lane & 3;
    const int rowb = rg * 32 + r;

    if (tid < ACT_D) {
        sPar[tid]       = bias[tid];
        sPar[256 + tid] = gam[tid];
        sPar[512 + tid] = bet[tid];
    }

    const uint32_t* aB0 = actu + (size_t)(rg * 16 + r) * PSTR + c * 4;
    const uint32_t* aB1 = aB0 + 8 * PSTR;

    float acc[2][4];
#pragma unroll
    for (int t = 0; t < 2; t++)
#pragma unroll
        for (int q = 0; q < 4; q++) acc[t][q] = 0.f;

    for (int ch = 0; ch < 8; ch++) {
        const uint32_t* wcur = (ch & 1) ? wb1 : wb0;
        if (ch + 1 < 8) {
            cp_chunk(((ch + 1) & 1) ? wb1 : wb0, wsrc + (size_t)(ch + 1) * CH_OUT, CH_OUT / 4);
            cp_commit();
            cp_wait1();
        } else {
            cp_wait0();
        }
        __syncthreads();
#pragma unroll
        for (int ks = 0; ks < 4; ks++) {
            uint4 a0 = *(const uint4*)(aB0 + (ch * 4 + ks) * 16);
            uint4 a1 = *(const uint4*)(aB1 + (ch * 4 + ks) * 16);
            uint2 bb = *(const uint2*)(wcur + (size_t)(wc * 8 + r) * WSTR + ks * 8 + 2 * c);
            mma8(acc[0], a0.x, a0.y, a0.z, a0.w, bb.x, bb.y);
            mma8(acc[1], a1.x, a1.y, a1.z, a1.w, bb.x, bb.y);
        }
        __syncthreads();
    }

    // ---- epilogue: bias + GN over 32 cols -> gmem fp32
    const int col = wc * 8 + 2 * c;
    float s[4], s2[4];
#pragma unroll
    for (int t = 0; t < 2; t++) {
        float d0 = acc[t][0] + sPar[col];
        float d1 = acc[t][1] + sPar[col + 1];
        float d2 = acc[t][2] + sPar[col];
        float d3 = acc[t][3] + sPar[col + 1];
        acc[t][0] = d0; acc[t][1] = d1; acc[t][2] = d2; acc[t][3] = d3;
        s[2 * t]     = d0 + d1;  s2[2 * t]     = d0 * d0 + d1 * d1;
        s[2 * t + 1] = d2 + d3;  s2[2 * t + 1] = d2 * d2 + d3 * d3;
    }
#pragma unroll
    for (int q = 0; q < 4; q++) {
        s[q]  += __shfl_xor_sync(0xffffffffu, s[q], 1);
        s2[q] += __shfl_xor_sync(0xffffffffu, s2[q], 1);
        s[q]  += __shfl_xor_sync(0xffffffffu, s[q], 2);
        s2[q] += __shfl_xor_sync(0xffffffffu, s2[q], 2);
    }
    if (c == 0) {
#pragma unroll
        for (int t = 0; t < 2; t++)
#pragma unroll
            for (int h = 0; h < 2; h++)
                sRed[(rowb + 16 * t + 8 * h) * 4 + wc] =
                    make_float2(s[2 * t + h], s2[2 * t + h]);
    }
    __syncthreads();
#pragma unroll
    for (int t = 0; t < 2; t++)
#pragma unroll
        for (int h = 0; h < 2; h++) {
            const int row = rowb + 16 * t + 8 * h;
            float2 p0 = sRed[row * 4 + 0], p1 = sRed[row * 4 + 1];
            float2 p2 = sRed[row * 4 + 2], p3 = sRed[row * 4 + 3];
            float S  = p0.x + p1.x + p2.x + p3.x;
            float S2 = p0.y + p1.y + p2.y + p3.y;
            float m  = S * (1.f / ACT_D);
            float v  = fmaxf(S2 * (1.f / ACT_D) - m * m, 0.f);
            float rstd = rsqrtf(v + 1e-5f);
            float2 o;
            o.x = (acc[t][2 * h]     - m) * rstd * sPar[256 + col]     + sPar[512 + col];
            o.y = (acc[t][2 * h + 1] - m) * rstd * sPar[256 + col + 1] + sPar[512 + col + 1];
            *(float2*)(out + (size_t)(b0 + row) * (NPOL * ACT_D) + (size_t)p * ACT_D + col) = o;
        }
}

// ---------------- main fused kernel: CTA = (policy, 128 batch rows)
__global__ void __launch_bounds__(NTHREADS, 1)
mlp_mma_kernel(const float* __restrict__ obs,
               const float* __restrict__ b1, const float* __restrict__ g1, const float* __restrict__ be1,
               const float* __restrict__ b2, const float* __restrict__ g2, const float* __restrict__ be2,
               const float* __restrict__ b3, const float* __restrict__ g3, const float* __restrict__ be3,
               const float* __restrict__ b4, const float* __restrict__ g4, const float* __restrict__ be4,
               float* __restrict__ out)
{
    extern __shared__ float smem[];
    uint32_t* actu = (uint32_t*)smem;                         // 64 * PSTR u32
    uint32_t* wb0  = actu + (size_t)64 * PSTR;                // CH_HID u32
    uint32_t* wb1  = wb0 + CH_HID;                            // CH_HID u32
    float*    sPar = (float*)(wb1 + CH_HID);                  // 768 floats
    float2*   sRed = (float2*)(sPar + 768);                   // 512 float2

    const int tid = threadIdx.x;
    const int p   = blockIdx.y;
    const int b0  = blockIdx.x * MT;
    const size_t pO = (size_t)p;

    // prefetch W1 chunk 0 immediately
    cp_chunk(wb0, gW1T + pO * 4 * CH_HID, CH_HID / 4);
    cp_commit();

    // stage observation tile [128,128] -> tf32, pair-row-interleaved blocks
    for (int i = tid; i < 64 * (OBS_D / 8); i += NTHREADS) {   // 1024 tasks
        int PR = i >> 4, o = i & 15;
        int g = PR >> 3, r = PR & 7;
        const float4* rA = (const float4*)(obs + (size_t)(b0 + g * 16 + r) * OBS_D + o * 8);
        const float4* rB = (const float4*)((const float*)rA + 8 * OBS_D);
        float4 f0 = rA[0], f1 = rA[1];
        float4 f2 = rB[0], f3 = rB[1];
        uint4* d = (uint4*)(actu + (size_t)PR * PSTR + o * 16);
        d[0] = make_uint4(f2tf32(f0.x), f2tf32(f2.x), f2tf32(f1.x), f2tf32(f3.x));
        d[1] = make_uint4(f2tf32(f0.y), f2tf32(f2.y), f2tf32(f1.y), f2tf32(f3.y));
        d[2] = make_uint4(f2tf32(f0.z), f2tf32(f2.z), f2tf32(f1.z), f2tf32(f3.z));
        d[3] = make_uint4(f2tf32(f0.w), f2tf32(f2.w), f2tf32(f1.w), f2tf32(f3.w));
    }
    // visibility: first __syncthreads inside layer_hidden's chunk loop

    layer_hidden<4>(gW1T + pO * 4 * CH_HID, gW2T + pO * 8 * CH_HID, CH_HID / 4,
                    b1 + pO * HID_D, g1 + pO * HID_D, be1 + pO * HID_D,
                    actu, wb0, wb1, sPar, sRed);
    layer_hidden<8>(gW2T + pO * 8 * CH_HID, gW3T + pO * 8 * CH_HID, CH_HID / 4,
                    b2 + pO * HID_D, g2 + pO * HID_D, be2 + pO * HID_D,
                    actu, wb0, wb1, sPar, sRed);
    layer_hidden<8>(gW3T + pO * 8 * CH_HID, gW4T + pO * 8 * CH_OUT, CH_OUT / 4,
                    b3 + pO * HID_D, g3 + pO * HID_D, be3 + pO * HID_D,
                    actu, wb0, wb1, sPar, sRed);
    layer_out(gW4T + pO * 8 * CH_OUT,
              b4 + pO * ACT_D, g4 + pO * ACT_D, be4 + pO * ACT_D,
              actu, wb0, wb1, sPar, sRed, out, p, b0);
}

// ---------------- launch
extern "C" void kernel_launch(void* const* d_in, const int* in_sizes, int n_in,
                              void* d_out, int out_size)
{
    const float* obs = (const float*)d_in[0];
    const float* W1  = (const float*)d_in[1];
    const float* b1  = (const float*)d_in[2];
    const float* g1  = (const float*)d_in[3];
    const float* be1 = (const float*)d_in[4];
    const float* W2  = (const float*)d_in[5];
    const float* b2  = (const float*)d_in[6];
    const float* g2  = (const float*)d_in[7];
    const float* be2 = (const float*)d_in[8];
    const float* W3  = (const float*)d_in[9];
    const float* b3  = (const float*)d_in[10];
    const float* g3  = (const float*)d_in[11];
    const float* be3 = (const float*)d_in[12];
    const float* W4  = (const float*)d_in[13];
    const float* b4  = (const float*)d_in[14];
    const float* g4  = (const float*)d_in[15];
    const float* be4 = (const float*)d_in[16];
    float* out = (float*)d_out;

    // merged prepass: 256 + 512 + 512 + 512 = 1792 chunk-blocks
    prep_all<<<1792, 256>>>(W1, W2, W3, W4);

    const int smem_bytes =
        (64 * PSTR + 2 * CH_HID + 768) * 4 + 512 * 8;   // 224256 B
    cudaFuncSetAttribute(mlp_mma_kernel,
                         cudaFuncAttributeMaxDynamicSharedMemorySize, smem_bytes);

    dim3 grid(NBATCH / MT, NPOL);   // 32 x 64 = 2048 CTAs
    mlp_mma_kernel<<<grid, NTHREADS, smem_bytes>>>(
        obs,
        b1, g1, be1,
        b2, g2, be2,
        b3, g3, be3,
        b4, g4, be4,
        out);
}